// round 3
// baseline (speedup 1.0000x reference)
#include <cuda_runtime.h>
#include <cstdint>

#define T_TOK   4096      // SL*BS tokens
#define HS      1024
#define FFN     4096
#define E_NUM   8
#define TOP_K   2
#define S_SLOTS (T_TOK * TOP_K)   // 8192 row slots

#define BM 128
#define BN 128
#define BK 16

// ---------------- device scratch (no allocations allowed) ----------------
__device__ int   g_cnt[E_NUM];
__device__ int   g_off[E_NUM];
__device__ int   g_tok[S_SLOTS];        // slot -> token id
__device__ float g_wt [S_SLOTS];        // slot -> gate weight
__device__ int   g_slot[S_SLOTS];       // (t*2+k) -> slot
__device__ float g_H[(size_t)S_SLOTS * FFN];  // 128 MB hidden activations
__device__ float g_Y[(size_t)S_SLOTS * HS];   // 32 MB per-slot outputs (weighted)

// ---------------- helpers ----------------
__device__ __forceinline__ unsigned long long pk2(float x) {
    unsigned long long r; unsigned xi = __float_as_uint(x);
    asm("mov.b64 %0, {%1, %1};" : "=l"(r) : "r"(xi));
    return r;
}
__device__ __forceinline__ void ffma2(unsigned long long& d,
                                      unsigned long long a,
                                      unsigned long long b) {
    asm("fma.rn.f32x2 %0, %1, %2, %0;" : "+l"(d) : "l"(a), "l"(b));
}
__device__ __forceinline__ float2 up2(unsigned long long v) {
    unsigned lo, hi;
    asm("mov.b64 {%0, %1}, %2;" : "=r"(lo), "=r"(hi) : "l"(v));
    return make_float2(__uint_as_float(lo), __uint_as_float(hi));
}
__device__ __forceinline__ float gelu_tanh(float v) {
    // jax.nn.gelu(approximate=True)
    float u = 0.7978845608028654f * (v + 0.044715f * v * v * v);
    return 0.5f * v * (1.0f + tanhf(u));
}

// ---------------- routing ----------------
__global__ void zero_cnt_kernel() {
    if (threadIdx.x < E_NUM) g_cnt[threadIdx.x] = 0;
}

__global__ void count_kernel(const int* __restrict__ ei) {
    int i = blockIdx.x * blockDim.x + threadIdx.x;
    if (i < S_SLOTS) atomicAdd(&g_cnt[ei[i]], 1);
}

__global__ void scan_kernel() {
    if (threadIdx.x == 0) {
        int acc = 0;
        for (int e = 0; e < E_NUM; e++) { g_off[e] = acc; acc += g_cnt[e]; }
    }
}

// Deterministic stable scatter: block e ranks all matching entries in index order.
__global__ void scatter_kernel(const int* __restrict__ ei,
                               const float* __restrict__ ew) {
    int e = blockIdx.x;
    __shared__ int warp_cnt[8];
    int t = threadIdx.x, lane = t & 31, w = t >> 5;
    int running = 0;
    int off = g_off[e];
    for (int c0 = 0; c0 < S_SLOTS; c0 += 256) {
        int i = c0 + t;
        int match = (ei[i] == e);
        unsigned mask = __ballot_sync(0xffffffffu, match);
        if (lane == 0) warp_cnt[w] = __popc(mask);
        __syncthreads();
        int wbase = 0, total = 0;
#pragma unroll
        for (int j = 0; j < 8; j++) {
            int c = warp_cnt[j];
            if (j < w) wbase += c;
            total += c;
        }
        if (match) {
            int rank = running + wbase + __popc(mask & ((1u << lane) - 1u));
            int slot = off + rank;
            g_tok[slot]  = i >> 1;     // token id
            g_wt[slot]   = ew[i];
            g_slot[i]    = slot;
        }
        running += total;
        __syncthreads();
    }
}

// ---------------- GEMM1: H = gelu(gather(x) @ w1[e]) ----------------
// grid: (FFN/BN, S/BM, E), block 256
__global__ __launch_bounds__(256, 2)
void gemm1_kernel(const float* __restrict__ x, const float* __restrict__ w1) {
    const int e  = blockIdx.z;
    const int mt = blockIdx.y;
    const int nt = blockIdx.x;
    const int cnt = g_cnt[e];
    if (mt * BM >= cnt) return;
    const int base = g_off[e] + mt * BM;

    __shared__ float As[BK][BM];
    __shared__ float Bs[BK][BN];
    __shared__ int   rows[BM];

    const int t = threadIdx.x;
    if (t < BM) {
        int idx = mt * BM + t;
        rows[t] = (idx < cnt) ? g_tok[base + t] : -1;
    }
    __syncthreads();

    // A-load mapping: 2 threads per row, 8 floats each (2x float4)
    const int am = t >> 1;
    const int ah = (t & 1) * 8;
    const int arow = rows[am];
    const float* aptr = (arow >= 0) ? (x + (size_t)arow * HS + ah) : nullptr;

    // B-load mapping: 16 threads per k-row, 8 floats each
    const int bk = t >> 4;
    const int bn = (t & 15) * 8;
    const float* bptr = w1 + (size_t)e * HS * FFN + (size_t)bk * FFN + nt * BN + bn;

    const int ty = t >> 4, tx = t & 15;
    const int m0 = ty * 8, n0 = tx * 8;

    unsigned long long acc[8][4];
#pragma unroll
    for (int i = 0; i < 8; i++)
#pragma unroll
        for (int j = 0; j < 4; j++) acc[i][j] = 0ull;

    for (int k0 = 0; k0 < HS; k0 += BK) {
        float4 av0 = make_float4(0.f, 0.f, 0.f, 0.f), av1 = av0;
        if (aptr) {
            av0 = *reinterpret_cast<const float4*>(aptr + k0);
            av1 = *reinterpret_cast<const float4*>(aptr + k0 + 4);
        }
        float4 bv0 = *reinterpret_cast<const float4*>(bptr + (size_t)k0 * FFN);
        float4 bv1 = *reinterpret_cast<const float4*>(bptr + (size_t)k0 * FFN + 4);
        __syncthreads();
        As[ah + 0][am] = av0.x; As[ah + 1][am] = av0.y;
        As[ah + 2][am] = av0.z; As[ah + 3][am] = av0.w;
        As[ah + 4][am] = av1.x; As[ah + 5][am] = av1.y;
        As[ah + 6][am] = av1.z; As[ah + 7][am] = av1.w;
        *reinterpret_cast<float4*>(&Bs[bk][bn])     = bv0;
        *reinterpret_cast<float4*>(&Bs[bk][bn + 4]) = bv1;
        __syncthreads();
#pragma unroll
        for (int kk = 0; kk < BK; kk++) {
            float4 a0 = *reinterpret_cast<const float4*>(&As[kk][m0]);
            float4 a1 = *reinterpret_cast<const float4*>(&As[kk][m0 + 4]);
            ulonglong2 bb0 = *reinterpret_cast<const ulonglong2*>(&Bs[kk][n0]);
            ulonglong2 bb1 = *reinterpret_cast<const ulonglong2*>(&Bs[kk][n0 + 4]);
            unsigned long long b2[4] = { bb0.x, bb0.y, bb1.x, bb1.y };
            float av[8] = { a0.x, a0.y, a0.z, a0.w, a1.x, a1.y, a1.z, a1.w };
#pragma unroll
            for (int i = 0; i < 8; i++) {
                unsigned long long a2 = pk2(av[i]);
#pragma unroll
                for (int j = 0; j < 4; j++) ffma2(acc[i][j], a2, b2[j]);
            }
        }
    }

    // epilogue: gelu, store to H
    const int mg = mt * BM + m0;
    const size_t col = (size_t)nt * BN + n0;
#pragma unroll
    for (int i = 0; i < 8; i++) {
        if (mg + i < cnt) {
            float* dst = g_H + (size_t)(base + m0 + i) * FFN + col;
            float2 p0 = up2(acc[i][0]), p1 = up2(acc[i][1]);
            float2 p2 = up2(acc[i][2]), p3 = up2(acc[i][3]);
            float4 o0 = make_float4(gelu_tanh(p0.x), gelu_tanh(p0.y),
                                    gelu_tanh(p1.x), gelu_tanh(p1.y));
            float4 o1 = make_float4(gelu_tanh(p2.x), gelu_tanh(p2.y),
                                    gelu_tanh(p3.x), gelu_tanh(p3.y));
            *reinterpret_cast<float4*>(dst)     = o0;
            *reinterpret_cast<float4*>(dst + 4) = o1;
        }
    }
}

// ---------------- GEMM2: Y = wt * (H @ w2[e]) ----------------
// grid: (HS/BN, S/BM, E), block 256
__global__ __launch_bounds__(256, 2)
void gemm2_kernel(const float* __restrict__ w2) {
    const int e  = blockIdx.z;
    const int mt = blockIdx.y;
    const int nt = blockIdx.x;
    const int cnt = g_cnt[e];
    if (mt * BM >= cnt) return;
    const int base = g_off[e] + mt * BM;

    __shared__ float As[BK][BM];
    __shared__ float Bs[BK][BN];

    const int t = threadIdx.x;

    const int am = t >> 1;
    const int ah = (t & 1) * 8;
    const bool avalid = (mt * BM + am) < cnt;
    const float* aptr = g_H + (size_t)(base + am) * FFN + ah;

    const int bk = t >> 4;
    const int bn = (t & 15) * 8;
    const float* bptr = w2 + (size_t)e * FFN * HS + (size_t)bk * HS + nt * BN + bn;

    const int ty = t >> 4, tx = t & 15;
    const int m0 = ty * 8, n0 = tx * 8;

    unsigned long long acc[8][4];
#pragma unroll
    for (int i = 0; i < 8; i++)
#pragma unroll
        for (int j = 0; j < 4; j++) acc[i][j] = 0ull;

    for (int k0 = 0; k0 < FFN; k0 += BK) {
        float4 av0 = make_float4(0.f, 0.f, 0.f, 0.f), av1 = av0;
        if (avalid) {
            av0 = *reinterpret_cast<const float4*>(aptr + k0);
            av1 = *reinterpret_cast<const float4*>(aptr + k0 + 4);
        }
        float4 bv0 = *reinterpret_cast<const float4*>(bptr + (size_t)k0 * HS);
        float4 bv1 = *reinterpret_cast<const float4*>(bptr + (size_t)k0 * HS + 4);
        __syncthreads();
        As[ah + 0][am] = av0.x; As[ah + 1][am] = av0.y;
        As[ah + 2][am] = av0.z; As[ah + 3][am] = av0.w;
        As[ah + 4][am] = av1.x; As[ah + 5][am] = av1.y;
        As[ah + 6][am] = av1.z; As[ah + 7][am] = av1.w;
        *reinterpret_cast<float4*>(&Bs[bk][bn])     = bv0;
        *reinterpret_cast<float4*>(&Bs[bk][bn + 4]) = bv1;
        __syncthreads();
#pragma unroll
        for (int kk = 0; kk < BK; kk++) {
            float4 a0 = *reinterpret_cast<const float4*>(&As[kk][m0]);
            float4 a1 = *reinterpret_cast<const float4*>(&As[kk][m0 + 4]);
            ulonglong2 bb0 = *reinterpret_cast<const ulonglong2*>(&Bs[kk][n0]);
            ulonglong2 bb1 = *reinterpret_cast<const ulonglong2*>(&Bs[kk][n0 + 4]);
            unsigned long long b2[4] = { bb0.x, bb0.y, bb1.x, bb1.y };
            float av[8] = { a0.x, a0.y, a0.z, a0.w, a1.x, a1.y, a1.z, a1.w };
#pragma unroll
            for (int i = 0; i < 8; i++) {
                unsigned long long a2 = pk2(av[i]);
#pragma unroll
                for (int j = 0; j < 4; j++) ffma2(acc[i][j], a2, b2[j]);
            }
        }
    }

    // epilogue: scale by gate weight, store per-slot output
    const int mg = mt * BM + m0;
    const size_t col = (size_t)nt * BN + n0;
#pragma unroll
    for (int i = 0; i < 8; i++) {
        if (mg + i < cnt) {
            int r = base + m0 + i;
            float wgt = g_wt[r];
            float* dst = g_Y + (size_t)r * HS + col;
            float2 p0 = up2(acc[i][0]), p1 = up2(acc[i][1]);
            float2 p2 = up2(acc[i][2]), p3 = up2(acc[i][3]);
            float4 o0 = make_float4(wgt * p0.x, wgt * p0.y, wgt * p1.x, wgt * p1.y);
            float4 o1 = make_float4(wgt * p2.x, wgt * p2.y, wgt * p3.x, wgt * p3.y);
            *reinterpret_cast<float4*>(dst)     = o0;
            *reinterpret_cast<float4*>(dst + 4) = o1;
        }
    }
}

// ---------------- combine: out[t] = Y[slot(t,0)] + Y[slot(t,1)] ----------------
__global__ void combine_kernel(float* __restrict__ out) {
    int i = blockIdx.x * blockDim.x + threadIdx.x;   // over T*HS/4 float4s
    if (i >= T_TOK * HS / 4) return;
    int tok = i / (HS / 4);
    int h4  = i - tok * (HS / 4);
    int s0 = g_slot[2 * tok];
    int s1 = g_slot[2 * tok + 1];
    const float4 y0 = *reinterpret_cast<const float4*>(g_Y + (size_t)s0 * HS + h4 * 4);
    const float4 y1 = *reinterpret_cast<const float4*>(g_Y + (size_t)s1 * HS + h4 * 4);
    float4 o = make_float4(y0.x + y1.x, y0.y + y1.y, y0.z + y1.z, y0.w + y1.w);
    reinterpret_cast<float4*>(out)[i] = o;
}

// ---------------- launch ----------------
extern "C" void kernel_launch(void* const* d_in, const int* in_sizes, int n_in,
                              void* d_out, int out_size) {
    const float* x  = (const float*)d_in[0];   // [4096, 1024]
    const float* ew = (const float*)d_in[1];   // [4096, 2]
    const int*   ei = (const int*)  d_in[2];   // [4096, 2]
    const float* w1 = (const float*)d_in[3];   // [8, 1024, 4096]
    const float* w2 = (const float*)d_in[4];   // [8, 4096, 1024]
    float* out = (float*)d_out;                // [4096, 1024]
    (void)in_sizes; (void)n_in; (void)out_size;

    zero_cnt_kernel<<<1, 32>>>();
    count_kernel<<<(S_SLOTS + 255) / 256, 256>>>(ei);
    scan_kernel<<<1, 32>>>();
    scatter_kernel<<<E_NUM, 256>>>(ei, ew);
    gemm1_kernel<<<dim3(FFN / BN, S_SLOTS / BM, E_NUM), 256>>>(x, w1);
    gemm2_kernel<<<dim3(HS / BN, S_SLOTS / BM, E_NUM), 256>>>(w2);
    combine_kernel<<<(T_TOK * HS / 4 + 255) / 256, 256>>>(out);
}

// round 6
// speedup vs baseline: 2.0104x; 2.0104x over previous
#include <cuda_runtime.h>
#include <cstdint>

#define T_TOK   4096
#define HS      1024
#define FFN     4096
#define E_NUM   8
#define S_SLOTS (T_TOK * 2)       // 8192
#define BM 128
#define BN 128
#define BK 32
#define ASTRIDE (BM + 8)          // 136 floats -> conflict-free fragment reads
#define BSTRIDE (BN + 8)
#define MAX_TILES (S_SLOTS / BM + E_NUM)   // 72

// ---------------- device scratch ----------------
__device__ int   g_cnt[E_NUM];
__device__ int   g_off[E_NUM];
__device__ int   g_ntiles;
__device__ int   g_tile_e[MAX_TILES];
__device__ int   g_tile_mt[MAX_TILES];
__device__ int   g_tok[S_SLOTS];
__device__ float g_wt [S_SLOTS];
__device__ int   g_slot[S_SLOTS];
__device__ float g_H[(size_t)S_SLOTS * FFN];   // 128 MB hidden acts (tf32-rounded)
__device__ float g_Y[(size_t)S_SLOTS * HS];    // 32 MB per-slot weighted outputs

// ---------------- helpers ----------------
__device__ __forceinline__ float to_tf32(float v) {
    uint32_t u;
    asm("cvt.rna.tf32.f32 %0, %1;" : "=r"(u) : "f"(v));
    return __uint_as_float(u);
}
__device__ __forceinline__ float gelu_tanh(float v) {
    float u = 0.7978845608028654f * (v + 0.044715f * v * v * v);
    return 0.5f * v * (1.0f + tanhf(u));
}
// D += A(16x8,row) * B(8x8,col), tf32 inputs, f32 accumulate. Cannot hang.
__device__ __forceinline__ void mma_tf32(float* c,
                                         uint32_t a0, uint32_t a1,
                                         uint32_t a2, uint32_t a3,
                                         uint32_t b0, uint32_t b1) {
    asm volatile(
        "mma.sync.aligned.m16n8k8.row.col.f32.tf32.tf32.f32 "
        "{%0,%1,%2,%3}, {%4,%5,%6,%7}, {%8,%9}, {%0,%1,%2,%3};\n"
        : "+f"(c[0]), "+f"(c[1]), "+f"(c[2]), "+f"(c[3])
        : "r"(a0), "r"(a1), "r"(a2), "r"(a3), "r"(b0), "r"(b1));
}

// ---------------- routing ----------------
__global__ void zero_cnt_kernel() {
    if (threadIdx.x < E_NUM) g_cnt[threadIdx.x] = 0;
}
__global__ void count_kernel(const int* __restrict__ ei) {
    int i = blockIdx.x * blockDim.x + threadIdx.x;
    if (i < S_SLOTS) atomicAdd(&g_cnt[ei[i]], 1);
}
__global__ void scan_kernel() {
    if (threadIdx.x == 0) {
        int acc = 0, nt = 0;
        for (int e = 0; e < E_NUM; e++) {
            g_off[e] = acc;
            int c = g_cnt[e];
            for (int mt = 0; mt * BM < c; mt++) {
                g_tile_e[nt] = e; g_tile_mt[nt] = mt; nt++;
            }
            acc += c;
        }
        g_ntiles = nt;
    }
}
__global__ void scatter_kernel(const int* __restrict__ ei,
                               const float* __restrict__ ew) {
    int e = blockIdx.x;
    __shared__ int warp_cnt[32];
    int t = threadIdx.x, lane = t & 31, w = t >> 5;
    int running = 0, off = g_off[e];
    for (int c0 = 0; c0 < S_SLOTS; c0 += 1024) {
        int i = c0 + t;
        int match = (ei[i] == e);
        unsigned mask = __ballot_sync(0xffffffffu, match);
        if (lane == 0) warp_cnt[w] = __popc(mask);
        __syncthreads();
        int wbase = 0, total = 0;
#pragma unroll
        for (int j = 0; j < 32; j++) {
            int c = warp_cnt[j];
            if (j < w) wbase += c;
            total += c;
        }
        if (match) {
            int rank = running + wbase + __popc(mask & ((1u << lane) - 1u));
            int slot = off + rank;
            g_tok[slot] = i >> 1;
            g_wt[slot]  = ew[i];
            g_slot[i]   = slot;
        }
        running += total;
        __syncthreads();
    }
}

// =====================================================================
// GEMM1: H = tf32round(gelu(gather(x) @ w1[e]))     [tiles x FFN/BN]
// grid: (FFN/BN, MAX_TILES), 256 threads, warp tile 32x64
// =====================================================================
__global__ __launch_bounds__(256, 2)
void gemm1_mma(const float* __restrict__ x, const float* __restrict__ w1) {
    const int ty = blockIdx.y;
    if (ty >= g_ntiles) return;
    const int e  = g_tile_e[ty];
    const int mt = g_tile_mt[ty];
    const int nt = blockIdx.x;
    const int cnt  = g_cnt[e];
    const int base = g_off[e] + mt * BM;

    __shared__ float As[BK][ASTRIDE];   // [k][m], 17.4 KB
    __shared__ float Bs[BK][BSTRIDE];   // [k][n], 17.4 KB
    __shared__ int   rows[BM];

    const int t = threadIdx.x;
    if (t < BM) rows[t] = (mt * BM + t < cnt) ? g_tok[base + t] : -1;
    __syncthreads();

    // A staging: 2 threads/row, 16 consecutive k each
    const int mrow = t >> 1, half = t & 1;
    const int arow = rows[mrow];
    const float* aptr = x + (size_t)(arow < 0 ? 0 : arow) * HS + half * 16;
    // B staging: 8 threads/k-row, 16 consecutive n each
    const int bk = t >> 3, bn = (t & 7) * 16;
    const float* bptr = w1 + (size_t)e * HS * FFN + (size_t)bk * FFN + nt * BN + bn;

    const int lane = t & 31, g = lane >> 2, tig = lane & 3;
    const int wm = (t >> 5 & 3) * 32;       // warp m offset (4 warps along m)
    const int wn = (t >> 7) * 64;           // warp n offset (2 warps along n)

    float acc[2][8][4];
#pragma unroll
    for (int mi = 0; mi < 2; mi++)
#pragma unroll
        for (int ni = 0; ni < 8; ni++)
#pragma unroll
            for (int j = 0; j < 4; j++) acc[mi][ni][j] = 0.f;

    float4 ra[4], rb[4];
#pragma unroll
    for (int q = 0; q < 4; q++) {
        ra[q] = (arow >= 0) ? *(const float4*)(aptr + q * 4) : make_float4(0, 0, 0, 0);
        rb[q] = *(const float4*)(bptr + q * 4);
    }

    const int S = HS / BK;   // 32 stages
    for (int s = 0; s < S; s++) {
        __syncthreads();
#pragma unroll
        for (int q = 0; q < 4; q++) {
            const int kq = half * 16 + q * 4;
            As[kq + 0][mrow] = to_tf32(ra[q].x);
            As[kq + 1][mrow] = to_tf32(ra[q].y);
            As[kq + 2][mrow] = to_tf32(ra[q].z);
            As[kq + 3][mrow] = to_tf32(ra[q].w);
            float4 vb = rb[q];
            vb.x = to_tf32(vb.x); vb.y = to_tf32(vb.y);
            vb.z = to_tf32(vb.z); vb.w = to_tf32(vb.w);
            *(float4*)&Bs[bk][bn + q * 4] = vb;
        }
        __syncthreads();
        if (s + 1 < S) {
            const int k0 = (s + 1) * BK;
#pragma unroll
            for (int q = 0; q < 4; q++) {
                ra[q] = (arow >= 0) ? *(const float4*)(aptr + k0 + q * 4)
                                    : make_float4(0, 0, 0, 0);
                rb[q] = *(const float4*)(bptr + (size_t)k0 * FFN + q * 4);
            }
        }
#pragma unroll
        for (int ks = 0; ks < 4; ks++) {
            const int kb = ks * 8;
            uint32_t a[2][4];
#pragma unroll
            for (int mi = 0; mi < 2; mi++) {
                const int m = wm + mi * 16 + g;
                a[mi][0] = __float_as_uint(As[kb + tig][m]);
                a[mi][1] = __float_as_uint(As[kb + tig][m + 8]);
                a[mi][2] = __float_as_uint(As[kb + tig + 4][m]);
                a[mi][3] = __float_as_uint(As[kb + tig + 4][m + 8]);
            }
#pragma unroll
            for (int ni = 0; ni < 8; ni++) {
                const int n = wn + ni * 8 + g;
                uint32_t b0 = __float_as_uint(Bs[kb + tig][n]);
                uint32_t b1 = __float_as_uint(Bs[kb + tig + 4][n]);
                mma_tf32(acc[0][ni], a[0][0], a[0][1], a[0][2], a[0][3], b0, b1);
                mma_tf32(acc[1][ni], a[1][0], a[1][1], a[1][2], a[1][3], b0, b1);
            }
        }
    }

    // epilogue: gelu + tf32 round, store to H
    const size_t ncol0 = (size_t)nt * BN + wn + 2 * tig;
#pragma unroll
    for (int mi = 0; mi < 2; mi++) {
        const int r0 = wm + mi * 16 + g;
        const int r1 = r0 + 8;
#pragma unroll
        for (int ni = 0; ni < 8; ni++) {
            const size_t nc = ncol0 + ni * 8;
            if (mt * BM + r0 < cnt) {
                float2 o0 = make_float2(to_tf32(gelu_tanh(acc[mi][ni][0])),
                                        to_tf32(gelu_tanh(acc[mi][ni][1])));
                *(float2*)(g_H + (size_t)(base + r0) * FFN + nc) = o0;
            }
            if (mt * BM + r1 < cnt) {
                float2 o1 = make_float2(to_tf32(gelu_tanh(acc[mi][ni][2])),
                                        to_tf32(gelu_tanh(acc[mi][ni][3])));
                *(float2*)(g_H + (size_t)(base + r1) * FFN + nc) = o1;
            }
        }
    }
}

// =====================================================================
// GEMM2: Y = wt * (H @ w2[e])     [tiles x HS/BN]
// =====================================================================
__global__ __launch_bounds__(256, 2)
void gemm2_mma(const float* __restrict__ w2) {
    const int ty = blockIdx.y;
    if (ty >= g_ntiles) return;
    const int e  = g_tile_e[ty];
    const int mt = g_tile_mt[ty];
    const int nt = blockIdx.x;
    const int cnt  = g_cnt[e];
    const int base = g_off[e] + mt * BM;

    __shared__ float As[BK][ASTRIDE];
    __shared__ float Bs[BK][BSTRIDE];

    const int t = threadIdx.x;
    const int mrow = t >> 1, half = t & 1;
    const bool avalid = (mt * BM + mrow) < cnt;
    const float* aptr = g_H + (size_t)(base + (avalid ? mrow : 0)) * FFN + half * 16;
    const int bk = t >> 3, bn = (t & 7) * 16;
    const float* bptr = w2 + (size_t)e * FFN * HS + (size_t)bk * HS + nt * BN + bn;

    const int lane = t & 31, g = lane >> 2, tig = lane & 3;
    const int wm = (t >> 5 & 3) * 32;
    const int wn = (t >> 7) * 64;

    float acc[2][8][4];
#pragma unroll
    for (int mi = 0; mi < 2; mi++)
#pragma unroll
        for (int ni = 0; ni < 8; ni++)
#pragma unroll
            for (int j = 0; j < 4; j++) acc[mi][ni][j] = 0.f;

    float4 ra[4], rb[4];
#pragma unroll
    for (int q = 0; q < 4; q++) {
        ra[q] = avalid ? *(const float4*)(aptr + q * 4) : make_float4(0, 0, 0, 0);
        rb[q] = *(const float4*)(bptr + q * 4);
    }

    const int S = FFN / BK;   // 128 stages
    for (int s = 0; s < S; s++) {
        __syncthreads();
#pragma unroll
        for (int q = 0; q < 4; q++) {
            const int kq = half * 16 + q * 4;
            // H already tf32-rounded at producer
            As[kq + 0][mrow] = ra[q].x;
            As[kq + 1][mrow] = ra[q].y;
            As[kq + 2][mrow] = ra[q].z;
            As[kq + 3][mrow] = ra[q].w;
            float4 vb = rb[q];
            vb.x = to_tf32(vb.x); vb.y = to_tf32(vb.y);
            vb.z = to_tf32(vb.z); vb.w = to_tf32(vb.w);
            *(float4*)&Bs[bk][bn + q * 4] = vb;
        }
        __syncthreads();
        if (s + 1 < S) {
            const int k0 = (s + 1) * BK;
#pragma unroll
            for (int q = 0; q < 4; q++) {
                ra[q] = avalid ? *(const float4*)(aptr + k0 + q * 4)
                               : make_float4(0, 0, 0, 0);
                rb[q] = *(const float4*)(bptr + (size_t)k0 * HS + q * 4);
            }
        }
#pragma unroll
        for (int ks = 0; ks < 4; ks++) {
            const int kb = ks * 8;
            uint32_t a[2][4];
#pragma unroll
            for (int mi = 0; mi < 2; mi++) {
                const int m = wm + mi * 16 + g;
                a[mi][0] = __float_as_uint(As[kb + tig][m]);
                a[mi][1] = __float_as_uint(As[kb + tig][m + 8]);
                a[mi][2] = __float_as_uint(As[kb + tig + 4][m]);
                a[mi][3] = __float_as_uint(As[kb + tig + 4][m + 8]);
            }
#pragma unroll
            for (int ni = 0; ni < 8; ni++) {
                const int n = wn + ni * 8 + g;
                uint32_t b0 = __float_as_uint(Bs[kb + tig][n]);
                uint32_t b1 = __float_as_uint(Bs[kb + tig + 4][n]);
                mma_tf32(acc[0][ni], a[0][0], a[0][1], a[0][2], a[0][3], b0, b1);
                mma_tf32(acc[1][ni], a[1][0], a[1][1], a[1][2], a[1][3], b0, b1);
            }
        }
    }

    // epilogue: scale by gate weight, store per-slot output
    const size_t ncol0 = (size_t)nt * BN + wn + 2 * tig;
#pragma unroll
    for (int mi = 0; mi < 2; mi++) {
        const int r0 = wm + mi * 16 + g;
        const int r1 = r0 + 8;
#pragma unroll
        for (int ni = 0; ni < 8; ni++) {
            const size_t nc = ncol0 + ni * 8;
            if (mt * BM + r0 < cnt) {
                float w = g_wt[base + r0];
                float2 o0 = make_float2(w * acc[mi][ni][0], w * acc[mi][ni][1]);
                *(float2*)(g_Y + (size_t)(base + r0) * HS + nc) = o0;
            }
            if (mt * BM + r1 < cnt) {
                float w = g_wt[base + r1];
                float2 o1 = make_float2(w * acc[mi][ni][2], w * acc[mi][ni][3]);
                *(float2*)(g_Y + (size_t)(base + r1) * HS + nc) = o1;
            }
        }
    }
}

// ---------------- combine: out[t] = Y[slot(t,0)] + Y[slot(t,1)] ----------------
__global__ void combine_kernel(float* __restrict__ out) {
    int i = blockIdx.x * blockDim.x + threadIdx.x;
    if (i >= T_TOK * HS / 4) return;
    int tok = i / (HS / 4);
    int h4  = i - tok * (HS / 4);
    int s0 = g_slot[2 * tok];
    int s1 = g_slot[2 * tok + 1];
    const float4 y0 = *(const float4*)(g_Y + (size_t)s0 * HS + h4 * 4);
    const float4 y1 = *(const float4*)(g_Y + (size_t)s1 * HS + h4 * 4);
    float4 o = make_float4(y0.x + y1.x, y0.y + y1.y, y0.z + y1.z, y0.w + y1.w);
    reinterpret_cast<float4*>(out)[i] = o;
}

// ---------------- launch ----------------
extern "C" void kernel_launch(void* const* d_in, const int* in_sizes, int n_in,
                              void* d_out, int out_size) {
    const float* x  = (const float*)d_in[0];   // [4096, 1024]
    const float* ew = (const float*)d_in[1];   // [4096, 2]
    const int*   ei = (const int*)  d_in[2];   // [4096, 2]
    const float* w1 = (const float*)d_in[3];   // [8, 1024, 4096]
    const float* w2 = (const float*)d_in[4];   // [8, 4096, 1024]
    float* out = (float*)d_out;
    (void)in_sizes; (void)n_in; (void)out_size;

    zero_cnt_kernel<<<1, 32>>>();
    count_kernel<<<(S_SLOTS + 255) / 256, 256>>>(ei);
    scan_kernel<<<1, 32>>>();
    scatter_kernel<<<E_NUM, 1024>>>(ei, ew);
    gemm1_mma<<<dim3(FFN / BN, MAX_TILES), 256>>>(x, w1);
    gemm2_mma<<<dim3(HS / BN, MAX_TILES), 256>>>(w2);
    combine_kernel<<<(T_TOK * HS / 4 + 255) / 256, 256>>>(out);
}

// round 7
// speedup vs baseline: 2.0552x; 1.0223x over previous
#include <cuda_runtime.h>
#include <cstdint>

#define T_TOK   4096
#define HS      1024
#define FFN     4096
#define E_NUM   8
#define S_SLOTS (T_TOK * 2)       // 8192
#define BM 128
#define BN 128
#define BK 32
#define ASTRIDE (BM + 8)          // 136 floats -> conflict-free fragment reads
#define BSTRIDE (BN + 8)
#define MAX_TILES (S_SLOTS / BM + E_NUM)   // 72

// dynamic-smem double-buffer layout (floats)
#define AOFF  (BK * ASTRIDE)              // 4352
#define BUFF  (BK * (ASTRIDE + BSTRIDE))  // 8704 floats per stage buffer
#define DB_BYTES (2 * BUFF * 4)           // 69632 bytes

// ---------------- device scratch ----------------
__device__ int   g_cnt[E_NUM];
__device__ int   g_off[E_NUM];
__device__ int   g_ntiles;
__device__ int   g_tile_e[MAX_TILES];
__device__ int   g_tile_mt[MAX_TILES];
__device__ int   g_tok[S_SLOTS];
__device__ float g_wt [S_SLOTS];
__device__ int   g_slot[S_SLOTS];
__device__ float g_H[(size_t)S_SLOTS * FFN];   // 128 MB hidden acts (tf32-rounded)
__device__ float g_Y[(size_t)S_SLOTS * HS];    // 32 MB per-slot weighted outputs

// ---------------- helpers ----------------
__device__ __forceinline__ float to_tf32(float v) {
    uint32_t u;
    asm("cvt.rna.tf32.f32 %0, %1;" : "=r"(u) : "f"(v));
    return __uint_as_float(u);
}
__device__ __forceinline__ float gelu_tanh(float v) {
    float u = 0.7978845608028654f * (v + 0.044715f * v * v * v);
    return 0.5f * v * (1.0f + tanhf(u));
}
__device__ __forceinline__ void mma_tf32(float* c,
                                         uint32_t a0, uint32_t a1,
                                         uint32_t a2, uint32_t a3,
                                         uint32_t b0, uint32_t b1) {
    asm volatile(
        "mma.sync.aligned.m16n8k8.row.col.f32.tf32.tf32.f32 "
        "{%0,%1,%2,%3}, {%4,%5,%6,%7}, {%8,%9}, {%0,%1,%2,%3};\n"
        : "+f"(c[0]), "+f"(c[1]), "+f"(c[2]), "+f"(c[3])
        : "r"(a0), "r"(a1), "r"(a2), "r"(a3), "r"(b0), "r"(b1));
}

// ---------------- routing ----------------
__global__ void zero_cnt_kernel() {
    if (threadIdx.x < E_NUM) g_cnt[threadIdx.x] = 0;
}
__global__ void count_kernel(const int* __restrict__ ei) {
    int i = blockIdx.x * blockDim.x + threadIdx.x;
    if (i < S_SLOTS) atomicAdd(&g_cnt[ei[i]], 1);
}
__global__ void scan_kernel() {
    if (threadIdx.x == 0) {
        int acc = 0, nt = 0;
        for (int e = 0; e < E_NUM; e++) {
            g_off[e] = acc;
            int c = g_cnt[e];
            for (int mt = 0; mt * BM < c; mt++) {
                g_tile_e[nt] = e; g_tile_mt[nt] = mt; nt++;
            }
            acc += c;
        }
        g_ntiles = nt;
    }
}
__global__ void scatter_kernel(const int* __restrict__ ei,
                               const float* __restrict__ ew) {
    int e = blockIdx.x;
    __shared__ int warp_cnt[32];
    int t = threadIdx.x, lane = t & 31, w = t >> 5;
    int running = 0, off = g_off[e];
    for (int c0 = 0; c0 < S_SLOTS; c0 += 1024) {
        int i = c0 + t;
        int match = (ei[i] == e);
        unsigned mask = __ballot_sync(0xffffffffu, match);
        if (lane == 0) warp_cnt[w] = __popc(mask);
        __syncthreads();
        int wbase = 0, total = 0;
#pragma unroll
        for (int j = 0; j < 32; j++) {
            int c = warp_cnt[j];
            if (j < w) wbase += c;
            total += c;
        }
        if (match) {
            int rank = running + wbase + __popc(mask & ((1u << lane) - 1u));
            int slot = off + rank;
            g_tok[slot] = i >> 1;
            g_wt[slot]  = ew[i];
            g_slot[i]   = slot;
        }
        running += total;
        __syncthreads();
    }
}

// =====================================================================
// Double-buffered GEMM1: H = tf32round(gelu(gather(x) @ w1[e]))
// grid: (FFN/BN, MAX_TILES), 256 threads, dynamic smem 69.6 KB
// =====================================================================
__global__ __launch_bounds__(256, 2)
void gemm1_db(const float* __restrict__ x, const float* __restrict__ w1) {
    const int ty = blockIdx.y;
    if (ty >= g_ntiles) return;
    const int e  = g_tile_e[ty];
    const int mt = g_tile_mt[ty];
    const int nt = blockIdx.x;
    const int cnt  = g_cnt[e];
    const int base = g_off[e] + mt * BM;

    extern __shared__ float sm[];
    __shared__ int rows[BM];

    const int t = threadIdx.x;
    if (t < BM) rows[t] = (mt * BM + t < cnt) ? g_tok[base + t] : -1;
    __syncthreads();

    const int mrow = t >> 1, half = t & 1;
    const int arow = rows[mrow];
    const float* aptr = x + (size_t)(arow < 0 ? 0 : arow) * HS + half * 16;
    const int bk = t >> 3, bn = (t & 7) * 16;
    const float* bptr = w1 + (size_t)e * HS * FFN + (size_t)bk * FFN + nt * BN + bn;

    const int lane = t & 31, g = lane >> 2, tig = lane & 3;
    const int wm = (t >> 5 & 3) * 32;
    const int wn = (t >> 7) * 64;

    float acc[2][8][4];
#pragma unroll
    for (int mi = 0; mi < 2; mi++)
#pragma unroll
        for (int ni = 0; ni < 8; ni++)
#pragma unroll
            for (int j = 0; j < 4; j++) acc[mi][ni][j] = 0.f;

    float4 ra[4], rb[4];
#pragma unroll
    for (int q = 0; q < 4; q++) {
        ra[q] = (arow >= 0) ? *(const float4*)(aptr + q * 4) : make_float4(0, 0, 0, 0);
        rb[q] = *(const float4*)(bptr + q * 4);
    }
    // prologue store -> buf0
    {
        float* Ac = sm;
        float* Bc = sm + AOFF;
#pragma unroll
        for (int q = 0; q < 4; q++) {
            const int kq = half * 16 + q * 4;
            Ac[(kq + 0) * ASTRIDE + mrow] = to_tf32(ra[q].x);
            Ac[(kq + 1) * ASTRIDE + mrow] = to_tf32(ra[q].y);
            Ac[(kq + 2) * ASTRIDE + mrow] = to_tf32(ra[q].z);
            Ac[(kq + 3) * ASTRIDE + mrow] = to_tf32(ra[q].w);
            float4 vb = rb[q];
            vb.x = to_tf32(vb.x); vb.y = to_tf32(vb.y);
            vb.z = to_tf32(vb.z); vb.w = to_tf32(vb.w);
            *(float4*)&Bc[bk * BSTRIDE + bn + q * 4] = vb;
        }
    }
    __syncthreads();

    const int S = HS / BK;   // 32 stages
    for (int s = 0; s < S; s++) {
        const bool more = (s + 1 < S);
        if (more) {
            const int k0 = (s + 1) * BK;
#pragma unroll
            for (int q = 0; q < 4; q++) {
                ra[q] = (arow >= 0) ? *(const float4*)(aptr + k0 + q * 4)
                                    : make_float4(0, 0, 0, 0);
                rb[q] = *(const float4*)(bptr + (size_t)k0 * FFN + q * 4);
            }
        }
        const float* Ac = sm + (s & 1) * BUFF;
        const float* Bc = Ac + AOFF;
#pragma unroll
        for (int ks = 0; ks < 4; ks++) {
            const int kb = ks * 8;
            uint32_t a[2][4];
#pragma unroll
            for (int mi = 0; mi < 2; mi++) {
                const int m = wm + mi * 16 + g;
                a[mi][0] = __float_as_uint(Ac[(kb + tig) * ASTRIDE + m]);
                a[mi][1] = __float_as_uint(Ac[(kb + tig) * ASTRIDE + m + 8]);
                a[mi][2] = __float_as_uint(Ac[(kb + tig + 4) * ASTRIDE + m]);
                a[mi][3] = __float_as_uint(Ac[(kb + tig + 4) * ASTRIDE + m + 8]);
            }
#pragma unroll
            for (int ni = 0; ni < 8; ni++) {
                const int n = wn + ni * 8 + g;
                uint32_t b0 = __float_as_uint(Bc[(kb + tig) * BSTRIDE + n]);
                uint32_t b1 = __float_as_uint(Bc[(kb + tig + 4) * BSTRIDE + n]);
                mma_tf32(acc[0][ni], a[0][0], a[0][1], a[0][2], a[0][3], b0, b1);
                mma_tf32(acc[1][ni], a[1][0], a[1][1], a[1][2], a[1][3], b0, b1);
            }
        }
        if (more) {
            float* An = sm + ((s + 1) & 1) * BUFF;
            float* Bn = An + AOFF;
#pragma unroll
            for (int q = 0; q < 4; q++) {
                const int kq = half * 16 + q * 4;
                An[(kq + 0) * ASTRIDE + mrow] = to_tf32(ra[q].x);
                An[(kq + 1) * ASTRIDE + mrow] = to_tf32(ra[q].y);
                An[(kq + 2) * ASTRIDE + mrow] = to_tf32(ra[q].z);
                An[(kq + 3) * ASTRIDE + mrow] = to_tf32(ra[q].w);
                float4 vb = rb[q];
                vb.x = to_tf32(vb.x); vb.y = to_tf32(vb.y);
                vb.z = to_tf32(vb.z); vb.w = to_tf32(vb.w);
                *(float4*)&Bn[bk * BSTRIDE + bn + q * 4] = vb;
            }
            __syncthreads();
        }
    }

    const size_t ncol0 = (size_t)nt * BN + wn + 2 * tig;
#pragma unroll
    for (int mi = 0; mi < 2; mi++) {
        const int r0 = wm + mi * 16 + g;
        const int r1 = r0 + 8;
#pragma unroll
        for (int ni = 0; ni < 8; ni++) {
            const size_t nc = ncol0 + ni * 8;
            if (mt * BM + r0 < cnt) {
                float2 o0 = make_float2(to_tf32(gelu_tanh(acc[mi][ni][0])),
                                        to_tf32(gelu_tanh(acc[mi][ni][1])));
                *(float2*)(g_H + (size_t)(base + r0) * FFN + nc) = o0;
            }
            if (mt * BM + r1 < cnt) {
                float2 o1 = make_float2(to_tf32(gelu_tanh(acc[mi][ni][2])),
                                        to_tf32(gelu_tanh(acc[mi][ni][3])));
                *(float2*)(g_H + (size_t)(base + r1) * FFN + nc) = o1;
            }
        }
    }
}

// =====================================================================
// Double-buffered GEMM2: Y = wt * (H @ w2[e])
// =====================================================================
__global__ __launch_bounds__(256, 2)
void gemm2_db(const float* __restrict__ w2) {
    const int ty = blockIdx.y;
    if (ty >= g_ntiles) return;
    const int e  = g_tile_e[ty];
    const int mt = g_tile_mt[ty];
    const int nt = blockIdx.x;
    const int cnt  = g_cnt[e];
    const int base = g_off[e] + mt * BM;

    extern __shared__ float sm[];

    const int t = threadIdx.x;
    const int mrow = t >> 1, half = t & 1;
    const bool avalid = (mt * BM + mrow) < cnt;
    const float* aptr = g_H + (size_t)(base + (avalid ? mrow : 0)) * FFN + half * 16;
    const int bk = t >> 3, bn = (t & 7) * 16;
    const float* bptr = w2 + (size_t)e * FFN * HS + (size_t)bk * HS + nt * BN + bn;

    const int lane = t & 31, g = lane >> 2, tig = lane & 3;
    const int wm = (t >> 5 & 3) * 32;
    const int wn = (t >> 7) * 64;

    float acc[2][8][4];
#pragma unroll
    for (int mi = 0; mi < 2; mi++)
#pragma unroll
        for (int ni = 0; ni < 8; ni++)
#pragma unroll
            for (int j = 0; j < 4; j++) acc[mi][ni][j] = 0.f;

    float4 ra[4], rb[4];
#pragma unroll
    for (int q = 0; q < 4; q++) {
        ra[q] = avalid ? *(const float4*)(aptr + q * 4) : make_float4(0, 0, 0, 0);
        rb[q] = *(const float4*)(bptr + q * 4);
    }
    {
        float* Ac = sm;
        float* Bc = sm + AOFF;
#pragma unroll
        for (int q = 0; q < 4; q++) {
            const int kq = half * 16 + q * 4;
            Ac[(kq + 0) * ASTRIDE + mrow] = ra[q].x;   // H pre-rounded
            Ac[(kq + 1) * ASTRIDE + mrow] = ra[q].y;
            Ac[(kq + 2) * ASTRIDE + mrow] = ra[q].z;
            Ac[(kq + 3) * ASTRIDE + mrow] = ra[q].w;
            float4 vb = rb[q];
            vb.x = to_tf32(vb.x); vb.y = to_tf32(vb.y);
            vb.z = to_tf32(vb.z); vb.w = to_tf32(vb.w);
            *(float4*)&Bc[bk * BSTRIDE + bn + q * 4] = vb;
        }
    }
    __syncthreads();

    const int S = FFN / BK;   // 128 stages
    for (int s = 0; s < S; s++) {
        const bool more = (s + 1 < S);
        if (more) {
            const int k0 = (s + 1) * BK;
#pragma unroll
            for (int q = 0; q < 4; q++) {
                ra[q] = avalid ? *(const float4*)(aptr + k0 + q * 4)
                               : make_float4(0, 0, 0, 0);
                rb[q] = *(const float4*)(bptr + (size_t)k0 * HS + q * 4);
            }
        }
        const float* Ac = sm + (s & 1) * BUFF;
        const float* Bc = Ac + AOFF;
#pragma unroll
        for (int ks = 0; ks < 4; ks++) {
            const int kb = ks * 8;
            uint32_t a[2][4];
#pragma unroll
            for (int mi = 0; mi < 2; mi++) {
                const int m = wm + mi * 16 + g;
                a[mi][0] = __float_as_uint(Ac[(kb + tig) * ASTRIDE + m]);
                a[mi][1] = __float_as_uint(Ac[(kb + tig) * ASTRIDE + m + 8]);
                a[mi][2] = __float_as_uint(Ac[(kb + tig + 4) * ASTRIDE + m]);
                a[mi][3] = __float_as_uint(Ac[(kb + tig + 4) * ASTRIDE + m + 8]);
            }
#pragma unroll
            for (int ni = 0; ni < 8; ni++) {
                const int n = wn + ni * 8 + g;
                uint32_t b0 = __float_as_uint(Bc[(kb + tig) * BSTRIDE + n]);
                uint32_t b1 = __float_as_uint(Bc[(kb + tig + 4) * BSTRIDE + n]);
                mma_tf32(acc[0][ni], a[0][0], a[0][1], a[0][2], a[0][3], b0, b1);
                mma_tf32(acc[1][ni], a[1][0], a[1][1], a[1][2], a[1][3], b0, b1);
            }
        }
        if (more) {
            float* An = sm + ((s + 1) & 1) * BUFF;
            float* Bn = An + AOFF;
#pragma unroll
            for (int q = 0; q < 4; q++) {
                const int kq = half * 16 + q * 4;
                An[(kq + 0) * ASTRIDE + mrow] = ra[q].x;
                An[(kq + 1) * ASTRIDE + mrow] = ra[q].y;
                An[(kq + 2) * ASTRIDE + mrow] = ra[q].z;
                An[(kq + 3) * ASTRIDE + mrow] = ra[q].w;
                float4 vb = rb[q];
                vb.x = to_tf32(vb.x); vb.y = to_tf32(vb.y);
                vb.z = to_tf32(vb.z); vb.w = to_tf32(vb.w);
                *(float4*)&Bn[bk * BSTRIDE + bn + q * 4] = vb;
            }
            __syncthreads();
        }
    }

    const size_t ncol0 = (size_t)nt * BN + wn + 2 * tig;
#pragma unroll
    for (int mi = 0; mi < 2; mi++) {
        const int r0 = wm + mi * 16 + g;
        const int r1 = r0 + 8;
#pragma unroll
        for (int ni = 0; ni < 8; ni++) {
            const size_t nc = ncol0 + ni * 8;
            if (mt * BM + r0 < cnt) {
                float w = g_wt[base + r0];
                float2 o0 = make_float2(w * acc[mi][ni][0], w * acc[mi][ni][1]);
                *(float2*)(g_Y + (size_t)(base + r0) * HS + nc) = o0;
            }
            if (mt * BM + r1 < cnt) {
                float w = g_wt[base + r1];
                float2 o1 = make_float2(w * acc[mi][ni][2], w * acc[mi][ni][3]);
                *(float2*)(g_Y + (size_t)(base + r1) * HS + nc) = o1;
            }
        }
    }
}

// =====================================================================
// Fallback (R5 proven): single-buffer static-smem GEMMs
// =====================================================================
__global__ __launch_bounds__(256, 2)
void gemm1_mma(const float* __restrict__ x, const float* __restrict__ w1) {
    const int ty = blockIdx.y;
    if (ty >= g_ntiles) return;
    const int e  = g_tile_e[ty];
    const int mt = g_tile_mt[ty];
    const int nt = blockIdx.x;
    const int cnt  = g_cnt[e];
    const int base = g_off[e] + mt * BM;

    __shared__ float As[BK][ASTRIDE];
    __shared__ float Bs[BK][BSTRIDE];
    __shared__ int   rows[BM];

    const int t = threadIdx.x;
    if (t < BM) rows[t] = (mt * BM + t < cnt) ? g_tok[base + t] : -1;
    __syncthreads();

    const int mrow = t >> 1, half = t & 1;
    const int arow = rows[mrow];
    const float* aptr = x + (size_t)(arow < 0 ? 0 : arow) * HS + half * 16;
    const int bk = t >> 3, bn = (t & 7) * 16;
    const float* bptr = w1 + (size_t)e * HS * FFN + (size_t)bk * FFN + nt * BN + bn;

    const int lane = t & 31, g = lane >> 2, tig = lane & 3;
    const int wm = (t >> 5 & 3) * 32;
    const int wn = (t >> 7) * 64;

    float acc[2][8][4];
#pragma unroll
    for (int mi = 0; mi < 2; mi++)
#pragma unroll
        for (int ni = 0; ni < 8; ni++)
#pragma unroll
            for (int j = 0; j < 4; j++) acc[mi][ni][j] = 0.f;

    float4 ra[4], rb[4];
#pragma unroll
    for (int q = 0; q < 4; q++) {
        ra[q] = (arow >= 0) ? *(const float4*)(aptr + q * 4) : make_float4(0, 0, 0, 0);
        rb[q] = *(const float4*)(bptr + q * 4);
    }

    const int S = HS / BK;
    for (int s = 0; s < S; s++) {
        __syncthreads();
#pragma unroll
        for (int q = 0; q < 4; q++) {
            const int kq = half * 16 + q * 4;
            As[kq + 0][mrow] = to_tf32(ra[q].x);
            As[kq + 1][mrow] = to_tf32(ra[q].y);
            As[kq + 2][mrow] = to_tf32(ra[q].z);
            As[kq + 3][mrow] = to_tf32(ra[q].w);
            float4 vb = rb[q];
            vb.x = to_tf32(vb.x); vb.y = to_tf32(vb.y);
            vb.z = to_tf32(vb.z); vb.w = to_tf32(vb.w);
            *(float4*)&Bs[bk][bn + q * 4] = vb;
        }
        __syncthreads();
        if (s + 1 < S) {
            const int k0 = (s + 1) * BK;
#pragma unroll
            for (int q = 0; q < 4; q++) {
                ra[q] = (arow >= 0) ? *(const float4*)(aptr + k0 + q * 4)
                                    : make_float4(0, 0, 0, 0);
                rb[q] = *(const float4*)(bptr + (size_t)k0 * FFN + q * 4);
            }
        }
#pragma unroll
        for (int ks = 0; ks < 4; ks++) {
            const int kb = ks * 8;
            uint32_t a[2][4];
#pragma unroll
            for (int mi = 0; mi < 2; mi++) {
                const int m = wm + mi * 16 + g;
                a[mi][0] = __float_as_uint(As[kb + tig][m]);
                a[mi][1] = __float_as_uint(As[kb + tig][m + 8]);
                a[mi][2] = __float_as_uint(As[kb + tig + 4][m]);
                a[mi][3] = __float_as_uint(As[kb + tig + 4][m + 8]);
            }
#pragma unroll
            for (int ni = 0; ni < 8; ni++) {
                const int n = wn + ni * 8 + g;
                uint32_t b0 = __float_as_uint(Bs[kb + tig][n]);
                uint32_t b1 = __float_as_uint(Bs[kb + tig + 4][n]);
                mma_tf32(acc[0][ni], a[0][0], a[0][1], a[0][2], a[0][3], b0, b1);
                mma_tf32(acc[1][ni], a[1][0], a[1][1], a[1][2], a[1][3], b0, b1);
            }
        }
    }

    const size_t ncol0 = (size_t)nt * BN + wn + 2 * tig;
#pragma unroll
    for (int mi = 0; mi < 2; mi++) {
        const int r0 = wm + mi * 16 + g;
        const int r1 = r0 + 8;
#pragma unroll
        for (int ni = 0; ni < 8; ni++) {
            const size_t nc = ncol0 + ni * 8;
            if (mt * BM + r0 < cnt) {
                float2 o0 = make_float2(to_tf32(gelu_tanh(acc[mi][ni][0])),
                                        to_tf32(gelu_tanh(acc[mi][ni][1])));
                *(float2*)(g_H + (size_t)(base + r0) * FFN + nc) = o0;
            }
            if (mt * BM + r1 < cnt) {
                float2 o1 = make_float2(to_tf32(gelu_tanh(acc[mi][ni][2])),
                                        to_tf32(gelu_tanh(acc[mi][ni][3])));
                *(float2*)(g_H + (size_t)(base + r1) * FFN + nc) = o1;
            }
        }
    }
}

__global__ __launch_bounds__(256, 2)
void gemm2_mma(const float* __restrict__ w2) {
    const int ty = blockIdx.y;
    if (ty >= g_ntiles) return;
    const int e  = g_tile_e[ty];
    const int mt = g_tile_mt[ty];
    const int nt = blockIdx.x;
    const int cnt  = g_cnt[e];
    const int base = g_off[e] + mt * BM;

    __shared__ float As[BK][ASTRIDE];
    __shared__ float Bs[BK][BSTRIDE];

    const int t = threadIdx.x;
    const int mrow = t >> 1, half = t & 1;
    const bool avalid = (mt * BM + mrow) < cnt;
    const float* aptr = g_H + (size_t)(base + (avalid ? mrow : 0)) * FFN + half * 16;
    const int bk = t >> 3, bn = (t & 7) * 16;
    const float* bptr = w2 + (size_t)e * FFN * HS + (size_t)bk * HS + nt * BN + bn;

    const int lane = t & 31, g = lane >> 2, tig = lane & 3;
    const int wm = (t >> 5 & 3) * 32;
    const int wn = (t >> 7) * 64;

    float acc[2][8][4];
#pragma unroll
    for (int mi = 0; mi < 2; mi++)
#pragma unroll
        for (int ni = 0; ni < 8; ni++)
#pragma unroll
            for (int j = 0; j < 4; j++) acc[mi][ni][j] = 0.f;

    float4 ra[4], rb[4];
#pragma unroll
    for (int q = 0; q < 4; q++) {
        ra[q] = avalid ? *(const float4*)(aptr + q * 4) : make_float4(0, 0, 0, 0);
        rb[q] = *(const float4*)(bptr + q * 4);
    }

    const int S = FFN / BK;
    for (int s = 0; s < S; s++) {
        __syncthreads();
#pragma unroll
        for (int q = 0; q < 4; q++) {
            const int kq = half * 16 + q * 4;
            As[kq + 0][mrow] = ra[q].x;
            As[kq + 1][mrow] = ra[q].y;
            As[kq + 2][mrow] = ra[q].z;
            As[kq + 3][mrow] = ra[q].w;
            float4 vb = rb[q];
            vb.x = to_tf32(vb.x); vb.y = to_tf32(vb.y);
            vb.z = to_tf32(vb.z); vb.w = to_tf32(vb.w);
            *(float4*)&Bs[bk][bn + q * 4] = vb;
        }
        __syncthreads();
        if (s + 1 < S) {
            const int k0 = (s + 1) * BK;
#pragma unroll
            for (int q = 0; q < 4; q++) {
                ra[q] = avalid ? *(const float4*)(aptr + k0 + q * 4)
                               : make_float4(0, 0, 0, 0);
                rb[q] = *(const float4*)(bptr + (size_t)k0 * HS + q * 4);
            }
        }
#pragma unroll
        for (int ks = 0; ks < 4; ks++) {
            const int kb = ks * 8;
            uint32_t a[2][4];
#pragma unroll
            for (int mi = 0; mi < 2; mi++) {
                const int m = wm + mi * 16 + g;
                a[mi][0] = __float_as_uint(As[kb + tig][m]);
                a[mi][1] = __float_as_uint(As[kb + tig][m + 8]);
                a[mi][2] = __float_as_uint(As[kb + tig + 4][m]);
                a[mi][3] = __float_as_uint(As[kb + tig + 4][m + 8]);
            }
#pragma unroll
            for (int ni = 0; ni < 8; ni++) {
                const int n = wn + ni * 8 + g;
                uint32_t b0 = __float_as_uint(Bs[kb + tig][n]);
                uint32_t b1 = __float_as_uint(Bs[kb + tig + 4][n]);
                mma_tf32(acc[0][ni], a[0][0], a[0][1], a[0][2], a[0][3], b0, b1);
                mma_tf32(acc[1][ni], a[1][0], a[1][1], a[1][2], a[1][3], b0, b1);
            }
        }
    }

    const size_t ncol0 = (size_t)nt * BN + wn + 2 * tig;
#pragma unroll
    for (int mi = 0; mi < 2; mi++) {
        const int r0 = wm + mi * 16 + g;
        const int r1 = r0 + 8;
#pragma unroll
        for (int ni = 0; ni < 8; ni++) {
            const size_t nc = ncol0 + ni * 8;
            if (mt * BM + r0 < cnt) {
                float w = g_wt[base + r0];
                float2 o0 = make_float2(w * acc[mi][ni][0], w * acc[mi][ni][1]);
                *(float2*)(g_Y + (size_t)(base + r0) * HS + nc) = o0;
            }
            if (mt * BM + r1 < cnt) {
                float w = g_wt[base + r1];
                float2 o1 = make_float2(w * acc[mi][ni][2], w * acc[mi][ni][3]);
                *(float2*)(g_Y + (size_t)(base + r1) * HS + nc) = o1;
            }
        }
    }
}

// ---------------- combine ----------------
__global__ void combine_kernel(float* __restrict__ out) {
    int i = blockIdx.x * blockDim.x + threadIdx.x;
    if (i >= T_TOK * HS / 4) return;
    int tok = i / (HS / 4);
    int h4  = i - tok * (HS / 4);
    int s0 = g_slot[2 * tok];
    int s1 = g_slot[2 * tok + 1];
    const float4 y0 = *(const float4*)(g_Y + (size_t)s0 * HS + h4 * 4);
    const float4 y1 = *(const float4*)(g_Y + (size_t)s1 * HS + h4 * 4);
    float4 o = make_float4(y0.x + y1.x, y0.y + y1.y, y0.z + y1.z, y0.w + y1.w);
    reinterpret_cast<float4*>(out)[i] = o;
}

// ---------------- launch ----------------
extern "C" void kernel_launch(void* const* d_in, const int* in_sizes, int n_in,
                              void* d_out, int out_size) {
    const float* x  = (const float*)d_in[0];
    const float* ew = (const float*)d_in[1];
    const int*   ei = (const int*)  d_in[2];
    const float* w1 = (const float*)d_in[3];
    const float* w2 = (const float*)d_in[4];
    float* out = (float*)d_out;
    (void)in_sizes; (void)n_in; (void)out_size;

    zero_cnt_kernel<<<1, 32>>>();
    count_kernel<<<(S_SLOTS + 255) / 256, 256>>>(ei);
    scan_kernel<<<1, 32>>>();
    scatter_kernel<<<E_NUM, 1024>>>(ei, ew);

    cudaError_t a1 = cudaFuncSetAttribute(
        gemm1_db, cudaFuncAttributeMaxDynamicSharedMemorySize, DB_BYTES);
    cudaError_t a2 = cudaFuncSetAttribute(
        gemm2_db, cudaFuncAttributeMaxDynamicSharedMemorySize, DB_BYTES);

    if (a1 == cudaSuccess && a2 == cudaSuccess) {
        gemm1_db<<<dim3(FFN / BN, MAX_TILES), 256, DB_BYTES>>>(x, w1);
        gemm2_db<<<dim3(HS / BN, MAX_TILES), 256, DB_BYTES>>>(w2);
    } else {
        gemm1_mma<<<dim3(FFN / BN, MAX_TILES), 256>>>(x, w1);
        gemm2_mma<<<dim3(HS / BN, MAX_TILES), 256>>>(w2);
    }
    combine_kernel<<<(T_TOK * HS / 4 + 255) / 256, 256>>>(out);
}

// round 9
// speedup vs baseline: 3.9154x; 1.9051x over previous
#include <cuda_runtime.h>
#include <cuda_fp16.h>
#include <cstdint>

#define T_TOK   4096
#define HS      1024
#define FFN     4096
#define E_NUM   8
#define S_SLOTS (T_TOK * 2)       // 8192
#define BM 128
#define BN 128
#define BK 32
#define KST  40                   // A row stride in halves: holds 32 k + pad; word bank
                                  // index = 20*m + tig -> bijective over 32 banks
#define BROW 136                  // B row stride in words (136 mod 32 = 8, conflict-free)
#define MAX_TILES (S_SLOTS / BM + E_NUM)   // 72

// ---------------- device scratch ----------------
__device__ int    g_cnt[E_NUM];
__device__ int    g_off[E_NUM];
__device__ int    g_ntiles;
__device__ int    g_tile_e[MAX_TILES];
__device__ int    g_tile_mt[MAX_TILES];
__device__ int    g_tok[S_SLOTS];
__device__ float  g_wt [S_SLOTS];
__device__ int    g_slot[S_SLOTS];
__device__ __half g_H[(size_t)S_SLOTS * FFN];  // 64 MB hidden acts (fp16)
__device__ float  g_Y[(size_t)S_SLOTS * HS];   // 32 MB per-slot weighted outputs

// ---------------- helpers ----------------
__device__ __forceinline__ float gelu_tanh(float v) {
    float u = 0.7978845608028654f * (v + 0.044715f * v * v * v);
    return 0.5f * v * (1.0f + tanhf(u));
}
// D += A(16x16,row) * B(16x8,col), f16 inputs, f32 accumulate
__device__ __forceinline__ void mma_f16(float* c,
                                        uint32_t a0, uint32_t a1,
                                        uint32_t a2, uint32_t a3,
                                        uint32_t b0, uint32_t b1) {
    asm volatile(
        "mma.sync.aligned.m16n8k16.row.col.f32.f16.f16.f32 "
        "{%0,%1,%2,%3}, {%4,%5,%6,%7}, {%8,%9}, {%0,%1,%2,%3};\n"
        : "+f"(c[0]), "+f"(c[1]), "+f"(c[2]), "+f"(c[3])
        : "r"(a0), "r"(a1), "r"(a2), "r"(a3), "r"(b0), "r"(b1));
}
// pack 8 consecutive-k floats (two float4) into 8 halves
__device__ __forceinline__ uint4 pack8(float4 a, float4 b) {
    __half2 h0 = __floats2half2_rn(a.x, a.y);
    __half2 h1 = __floats2half2_rn(a.z, a.w);
    __half2 h2 = __floats2half2_rn(b.x, b.y);
    __half2 h3 = __floats2half2_rn(b.z, b.w);
    uint4 r;
    r.x = *reinterpret_cast<uint32_t*>(&h0);
    r.y = *reinterpret_cast<uint32_t*>(&h1);
    r.z = *reinterpret_cast<uint32_t*>(&h2);
    r.w = *reinterpret_cast<uint32_t*>(&h3);
    return r;
}
// pack (row k, row k+1) x 4 n-values into 4 half2 (lo=even k, hi=odd k)
__device__ __forceinline__ uint4 packB(float4 r0, float4 r1) {
    __half2 h0 = __floats2half2_rn(r0.x, r1.x);
    __half2 h1 = __floats2half2_rn(r0.y, r1.y);
    __half2 h2 = __floats2half2_rn(r0.z, r1.z);
    __half2 h3 = __floats2half2_rn(r0.w, r1.w);
    uint4 r;
    r.x = *reinterpret_cast<uint32_t*>(&h0);
    r.y = *reinterpret_cast<uint32_t*>(&h1);
    r.z = *reinterpret_cast<uint32_t*>(&h2);
    r.w = *reinterpret_cast<uint32_t*>(&h3);
    return r;
}

// ---------------- routing ----------------
__global__ void zero_cnt_kernel() {
    if (threadIdx.x < E_NUM) g_cnt[threadIdx.x] = 0;
}
__global__ void count_kernel(const int* __restrict__ ei) {
    int i = blockIdx.x * blockDim.x + threadIdx.x;
    if (i < S_SLOTS) atomicAdd(&g_cnt[ei[i]], 1);
}
__global__ void scan_kernel() {
    if (threadIdx.x == 0) {
        int acc = 0, nt = 0;
        for (int e = 0; e < E_NUM; e++) {
            g_off[e] = acc;
            int c = g_cnt[e];
            for (int mt = 0; mt * BM < c; mt++) {
                g_tile_e[nt] = e; g_tile_mt[nt] = mt; nt++;
            }
            acc += c;
        }
        g_ntiles = nt;
    }
}
__global__ void scatter_kernel(const int* __restrict__ ei,
                               const float* __restrict__ ew) {
    int e = blockIdx.x;
    __shared__ int warp_cnt[32];
    int t = threadIdx.x, lane = t & 31, w = t >> 5;
    int running = 0, off = g_off[e];
    for (int c0 = 0; c0 < S_SLOTS; c0 += 1024) {
        int i = c0 + t;
        int match = (ei[i] == e);
        unsigned mask = __ballot_sync(0xffffffffu, match);
        if (lane == 0) warp_cnt[w] = __popc(mask);
        __syncthreads();
        int wbase = 0, total = 0;
#pragma unroll
        for (int j = 0; j < 32; j++) {
            int c = warp_cnt[j];
            if (j < w) wbase += c;
            total += c;
        }
        if (match) {
            int rank = running + wbase + __popc(mask & ((1u << lane) - 1u));
            int slot = off + rank;
            g_tok[slot] = i >> 1;
            g_wt[slot]  = ew[i];
            g_slot[i]   = slot;
        }
        running += total;
        __syncthreads();
    }
}

// =====================================================================
// GEMM1 (fp16 mma, double-buffered): H = f16(gelu(gather(x) @ w1[e]))
// grid: (FFN/BN, MAX_TILES), 256 threads
// =====================================================================
__global__ __launch_bounds__(256, 2)
void gemm1_f16(const float* __restrict__ x, const float* __restrict__ w1) {
    const int ty = blockIdx.y;
    if (ty >= g_ntiles) return;
    const int e  = g_tile_e[ty];
    const int mt = g_tile_mt[ty];
    const int nt = blockIdx.x;
    const int cnt  = g_cnt[e];
    const int base = g_off[e] + mt * BM;

    __shared__ __align__(16) __half   As[2][BM][KST];        // 20 KB
    __shared__ __align__(16) uint32_t Bs[2][BK / 2][BROW];   // 17 KB (half2 k-pairs)
    __shared__ int rows[BM];

    const int t = threadIdx.x;
    if (t < BM) rows[t] = (mt * BM + t < cnt) ? g_tok[base + t] : -1;
    __syncthreads();

    // A staging: 2 threads/row, 16 consecutive k each (halves 0..15 / 16..31)
    const int mrow = t >> 1, ah = t & 1;
    const int arow = rows[mrow];
    const float* aptr = x + (size_t)(arow < 0 ? 0 : arow) * HS + ah * 16;
    // B staging: thread handles half2-row bkk (k rows 2bkk, 2bkk+1), 8 n values
    const int bkk = t >> 4, bn = (t & 15) * 8;
    const float* bptr = w1 + (size_t)e * HS * FFN
                           + (size_t)(2 * bkk) * FFN + nt * BN + bn;

    const int lane = t & 31, g = lane >> 2, tig = lane & 3;
    const int wm = (t >> 5 & 3) * 32;
    const int wn = (t >> 7) * 64;

    float acc[2][8][4];
#pragma unroll
    for (int mi = 0; mi < 2; mi++)
#pragma unroll
        for (int ni = 0; ni < 8; ni++)
#pragma unroll
            for (int j = 0; j < 4; j++) acc[mi][ni][j] = 0.f;

    float4 ra0, ra1, ra2, ra3, rb00, rb01, rb10, rb11;
    {
        const float4 z = make_float4(0, 0, 0, 0);
        ra0 = (arow >= 0) ? *(const float4*)(aptr + 0)  : z;
        ra1 = (arow >= 0) ? *(const float4*)(aptr + 4)  : z;
        ra2 = (arow >= 0) ? *(const float4*)(aptr + 8)  : z;
        ra3 = (arow >= 0) ? *(const float4*)(aptr + 12) : z;
        rb00 = *(const float4*)(bptr);
        rb01 = *(const float4*)(bptr + 4);
        rb10 = *(const float4*)(bptr + FFN);
        rb11 = *(const float4*)(bptr + FFN + 4);
    }
    *(uint4*)&As[0][mrow][ah * 16]     = pack8(ra0, ra1);
    *(uint4*)&As[0][mrow][ah * 16 + 8] = pack8(ra2, ra3);
    *(uint4*)&Bs[0][bkk][bn]           = packB(rb00, rb10);
    *(uint4*)&Bs[0][bkk][bn + 4]       = packB(rb01, rb11);
    __syncthreads();

    const int S = HS / BK;   // 32 stages
    for (int s = 0; s < S; s++) {
        const int buf = s & 1;
        const bool more = (s + 1 < S);
        if (more) {
            const int k0 = (s + 1) * BK;
            const float4 z = make_float4(0, 0, 0, 0);
            ra0 = (arow >= 0) ? *(const float4*)(aptr + k0 + 0)  : z;
            ra1 = (arow >= 0) ? *(const float4*)(aptr + k0 + 4)  : z;
            ra2 = (arow >= 0) ? *(const float4*)(aptr + k0 + 8)  : z;
            ra3 = (arow >= 0) ? *(const float4*)(aptr + k0 + 12) : z;
            const float* bp = bptr + (size_t)k0 * FFN;
            rb00 = *(const float4*)(bp);
            rb01 = *(const float4*)(bp + 4);
            rb10 = *(const float4*)(bp + FFN);
            rb11 = *(const float4*)(bp + FFN + 4);
        }
#pragma unroll
        for (int ks = 0; ks < 2; ks++) {
            const int kb = ks * 16;   // k offset (halves)
            const int kk = ks * 8;    // B half2-row offset
            uint32_t a[2][4];
#pragma unroll
            for (int mi = 0; mi < 2; mi++) {
                const int m = wm + mi * 16 + g;
                a[mi][0] = *(const uint32_t*)&As[buf][m][kb + 2 * tig];
                a[mi][1] = *(const uint32_t*)&As[buf][m + 8][kb + 2 * tig];
                a[mi][2] = *(const uint32_t*)&As[buf][m][kb + 2 * tig + 8];
                a[mi][3] = *(const uint32_t*)&As[buf][m + 8][kb + 2 * tig + 8];
            }
#pragma unroll
            for (int ni = 0; ni < 8; ni++) {
                const int n = wn + ni * 8 + g;
                uint32_t b0 = Bs[buf][kk + tig][n];
                uint32_t b1 = Bs[buf][kk + tig + 4][n];
                mma_f16(acc[0][ni], a[0][0], a[0][1], a[0][2], a[0][3], b0, b1);
                mma_f16(acc[1][ni], a[1][0], a[1][1], a[1][2], a[1][3], b0, b1);
            }
        }
        if (more) {
            const int nb = buf ^ 1;
            *(uint4*)&As[nb][mrow][ah * 16]     = pack8(ra0, ra1);
            *(uint4*)&As[nb][mrow][ah * 16 + 8] = pack8(ra2, ra3);
            *(uint4*)&Bs[nb][bkk][bn]           = packB(rb00, rb10);
            *(uint4*)&Bs[nb][bkk][bn + 4]       = packB(rb01, rb11);
            __syncthreads();
        }
    }

    // epilogue: gelu -> fp16, store to H
    const int ncol0 = nt * BN + wn + 2 * tig;
#pragma unroll
    for (int mi = 0; mi < 2; mi++) {
        const int r0 = wm + mi * 16 + g;
        const int r1 = r0 + 8;
#pragma unroll
        for (int ni = 0; ni < 8; ni++) {
            const int nc = ncol0 + ni * 8;
            if (mt * BM + r0 < cnt) {
                __half2 o = __floats2half2_rn(gelu_tanh(acc[mi][ni][0]),
                                              gelu_tanh(acc[mi][ni][1]));
                *(__half2*)&g_H[(size_t)(base + r0) * FFN + nc] = o;
            }
            if (mt * BM + r1 < cnt) {
                __half2 o = __floats2half2_rn(gelu_tanh(acc[mi][ni][2]),
                                              gelu_tanh(acc[mi][ni][3]));
                *(__half2*)&g_H[(size_t)(base + r1) * FFN + nc] = o;
            }
        }
    }
}

// =====================================================================
// GEMM2 (fp16 mma, double-buffered): Y = wt * (H @ w2[e])
// =====================================================================
__global__ __launch_bounds__(256, 2)
void gemm2_f16(const float* __restrict__ w2) {
    const int ty = blockIdx.y;
    if (ty >= g_ntiles) return;
    const int e  = g_tile_e[ty];
    const int mt = g_tile_mt[ty];
    const int nt = blockIdx.x;
    const int cnt  = g_cnt[e];
    const int base = g_off[e] + mt * BM;

    __shared__ __align__(16) __half   As[2][BM][KST];
    __shared__ __align__(16) uint32_t Bs[2][BK / 2][BROW];

    const int t = threadIdx.x;
    const int mrow = t >> 1, ah = t & 1;
    const bool avalid = (mt * BM + mrow) < cnt;
    const __half* aptr = g_H + (size_t)(base + (avalid ? mrow : 0)) * FFN + ah * 16;
    const int bkk = t >> 4, bn = (t & 15) * 8;
    const float* bptr = w2 + (size_t)e * FFN * HS
                           + (size_t)(2 * bkk) * HS + nt * BN + bn;

    const int lane = t & 31, g = lane >> 2, tig = lane & 3;
    const int wm = (t >> 5 & 3) * 32;
    const int wn = (t >> 7) * 64;

    float acc[2][8][4];
#pragma unroll
    for (int mi = 0; mi < 2; mi++)
#pragma unroll
        for (int ni = 0; ni < 8; ni++)
#pragma unroll
            for (int j = 0; j < 4; j++) acc[mi][ni][j] = 0.f;

    uint4 ua0, ua1;
    float4 rb00, rb01, rb10, rb11;
    {
        const uint4 uz = make_uint4(0, 0, 0, 0);
        ua0 = avalid ? *(const uint4*)(aptr)     : uz;
        ua1 = avalid ? *(const uint4*)(aptr + 8) : uz;
        rb00 = *(const float4*)(bptr);
        rb01 = *(const float4*)(bptr + 4);
        rb10 = *(const float4*)(bptr + HS);
        rb11 = *(const float4*)(bptr + HS + 4);
    }
    *(uint4*)&As[0][mrow][ah * 16]     = ua0;
    *(uint4*)&As[0][mrow][ah * 16 + 8] = ua1;
    *(uint4*)&Bs[0][bkk][bn]           = packB(rb00, rb10);
    *(uint4*)&Bs[0][bkk][bn + 4]       = packB(rb01, rb11);
    __syncthreads();

    const int S = FFN / BK;   // 128 stages
    for (int s = 0; s < S; s++) {
        const int buf = s & 1;
        const bool more = (s + 1 < S);
        if (more) {
            const int k0 = (s + 1) * BK;
            const uint4 uz = make_uint4(0, 0, 0, 0);
            ua0 = avalid ? *(const uint4*)(aptr + k0)     : uz;
            ua1 = avalid ? *(const uint4*)(aptr + k0 + 8) : uz;
            const float* bp = bptr + (size_t)k0 * HS;
            rb00 = *(const float4*)(bp);
            rb01 = *(const float4*)(bp + 4);
            rb10 = *(const float4*)(bp + HS);
            rb11 = *(const float4*)(bp + HS + 4);
        }
#pragma unroll
        for (int ks = 0; ks < 2; ks++) {
            const int kb = ks * 16;
            const int kk = ks * 8;
            uint32_t a[2][4];
#pragma unroll
            for (int mi = 0; mi < 2; mi++) {
                const int m = wm + mi * 16 + g;
                a[mi][0] = *(const uint32_t*)&As[buf][m][kb + 2 * tig];
                a[mi][1] = *(const uint32_t*)&As[buf][m + 8][kb + 2 * tig];
                a[mi][2] = *(const uint32_t*)&As[buf][m][kb + 2 * tig + 8];
                a[mi][3] = *(const uint32_t*)&As[buf][m + 8][kb + 2 * tig + 8];
            }
#pragma unroll
            for (int ni = 0; ni < 8; ni++) {
                const int n = wn + ni * 8 + g;
                uint32_t b0 = Bs[buf][kk + tig][n];
                uint32_t b1 = Bs[buf][kk + tig + 4][n];
                mma_f16(acc[0][ni], a[0][0], a[0][1], a[0][2], a[0][3], b0, b1);
                mma_f16(acc[1][ni], a[1][0], a[1][1], a[1][2], a[1][3], b0, b1);
            }
        }
        if (more) {
            const int nb = buf ^ 1;
            *(uint4*)&As[nb][mrow][ah * 16]     = ua0;
            *(uint4*)&As[nb][mrow][ah * 16 + 8] = ua1;
            *(uint4*)&Bs[nb][bkk][bn]           = packB(rb00, rb10);
            *(uint4*)&Bs[nb][bkk][bn + 4]       = packB(rb01, rb11);
            __syncthreads();
        }
    }

    // epilogue: scale by gate weight, store per-slot output (f32)
    const int ncol0 = nt * BN + wn + 2 * tig;
#pragma unroll
    for (int mi = 0; mi < 2; mi++) {
        const int r0 = wm + mi * 16 + g;
        const int r1 = r0 + 8;
#pragma unroll
        for (int ni = 0; ni < 8; ni++) {
            const int nc = ncol0 + ni * 8;
            if (mt * BM + r0 < cnt) {
                float w = g_wt[base + r0];
                float2 o = make_float2(w * acc[mi][ni][0], w * acc[mi][ni][1]);
                *(float2*)&g_Y[(size_t)(base + r0) * HS + nc] = o;
            }
            if (mt * BM + r1 < cnt) {
                float w = g_wt[base + r1];
                float2 o = make_float2(w * acc[mi][ni][2], w * acc[mi][ni][3]);
                *(float2*)&g_Y[(size_t)(base + r1) * HS + nc] = o;
            }
        }
    }
}

// ---------------- combine: out[t] = Y[slot(t,0)] + Y[slot(t,1)] ----------------
__global__ void combine_kernel(float* __restrict__ out) {
    int i = blockIdx.x * blockDim.x + threadIdx.x;
    if (i >= T_TOK * HS / 4) return;
    int tok = i / (HS / 4);
    int h4  = i - tok * (HS / 4);
    int s0 = g_slot[2 * tok];
    int s1 = g_slot[2 * tok + 1];
    const float4 y0 = *(const float4*)(g_Y + (size_t)s0 * HS + h4 * 4);
    const float4 y1 = *(const float4*)(g_Y + (size_t)s1 * HS + h4 * 4);
    float4 o = make_float4(y0.x + y1.x, y0.y + y1.y, y0.z + y1.z, y0.w + y1.w);
    reinterpret_cast<float4*>(out)[i] = o;
}

// ---------------- launch ----------------
extern "C" void kernel_launch(void* const* d_in, const int* in_sizes, int n_in,
                              void* d_out, int out_size) {
    const float* x  = (const float*)d_in[0];   // [4096, 1024]
    const float* ew = (const float*)d_in[1];   // [4096, 2]
    const int*   ei = (const int*)  d_in[2];   // [4096, 2]
    const float* w1 = (const float*)d_in[3];   // [8, 1024, 4096]
    const float* w2 = (const float*)d_in[4];   // [8, 4096, 1024]
    float* out = (float*)d_out;
    (void)in_sizes; (void)n_in; (void)out_size;

    zero_cnt_kernel<<<1, 32>>>();
    count_kernel<<<(S_SLOTS + 255) / 256, 256>>>(ei);
    scan_kernel<<<1, 32>>>();
    scatter_kernel<<<E_NUM, 1024>>>(ei, ew);
    gemm1_f16<<<dim3(FFN / BN, MAX_TILES), 256>>>(x, w1);
    gemm2_f16<<<dim3(HS / BN, MAX_TILES), 256>>>(w2);
    combine_kernel<<<(T_TOK * HS / 4 + 255) / 256, 256>>>(out);
}

// round 14
// speedup vs baseline: 4.2824x; 1.0937x over previous
#include <cuda_runtime.h>
#include <cuda_fp16.h>
#include <cstdint>

#define T_TOK   4096
#define HS      1024
#define FFN     4096
#define E_NUM   8
#define S_SLOTS (T_TOK * 2)       // 8192
#define BM 256
#define BN 128
#define BK 32
#define KST  40                   // A row stride in halves (word bank = 20m+tig, bijective)
#define BROW 136                  // B row stride in words (8*tig+g bijective)
#define MAX_TILES (S_SLOTS / BM + E_NUM)   // 40

// dynamic smem layout (bytes): Bs then As, both double-buffered
#define BS_WORDS_PER_BUF (16 * BROW)           // 2176
#define AS_HALF_PER_BUF  (BM * KST)            // 10240
#define BS_BYTES (2 * BS_WORDS_PER_BUF * 4)    // 17408
#define AS_BYTES (2 * AS_HALF_PER_BUF * 2)     // 40960
#define SMEM_BYTES (BS_BYTES + AS_BYTES)       // 58368

// ---------------- device scratch ----------------
__device__ int    g_cnt[E_NUM];
__device__ int    g_off[E_NUM];
__device__ int    g_ntiles;
__device__ int    g_tile_e[MAX_TILES];
__device__ int    g_tile_mt[MAX_TILES];
__device__ int    g_tok[S_SLOTS];
__device__ float  g_wt [S_SLOTS];
__device__ int    g_slot[S_SLOTS];
__device__ __half g_xh[(size_t)T_TOK * HS];    // 8 MB fp16 copy of x
__device__ __half g_H [(size_t)S_SLOTS * FFN]; // 64 MB hidden acts (fp16)
__device__ float  g_Y [(size_t)S_SLOTS * HS];  // 32 MB per-slot outputs

// ---------------- helpers ----------------
__device__ __forceinline__ float gelu_tanh(float v) {
    float u = 0.7978845608028654f * (v + 0.044715f * v * v * v);
    return 0.5f * v * (1.0f + tanhf(u));
}
__device__ __forceinline__ void mma_f16(float* c,
                                        uint32_t a0, uint32_t a1,
                                        uint32_t a2, uint32_t a3,
                                        uint32_t b0, uint32_t b1) {
    asm volatile(
        "mma.sync.aligned.m16n8k16.row.col.f32.f16.f16.f32 "
        "{%0,%1,%2,%3}, {%4,%5,%6,%7}, {%8,%9}, {%0,%1,%2,%3};\n"
        : "+f"(c[0]), "+f"(c[1]), "+f"(c[2]), "+f"(c[3])
        : "r"(a0), "r"(a1), "r"(a2), "r"(a3), "r"(b0), "r"(b1));
}
// pack (row k, row k+1) x 4 n-values into 4 half2 (lo=even k, hi=odd k)
__device__ __forceinline__ uint4 packB(float4 r0, float4 r1) {
    __half2 h0 = __floats2half2_rn(r0.x, r1.x);
    __half2 h1 = __floats2half2_rn(r0.y, r1.y);
    __half2 h2 = __floats2half2_rn(r0.z, r1.z);
    __half2 h3 = __floats2half2_rn(r0.w, r1.w);
    uint4 r;
    r.x = *reinterpret_cast<uint32_t*>(&h0);
    r.y = *reinterpret_cast<uint32_t*>(&h1);
    r.z = *reinterpret_cast<uint32_t*>(&h2);
    r.w = *reinterpret_cast<uint32_t*>(&h3);
    return r;
}

// ---------------- routing ----------------
__global__ void zero_cnt_kernel() {
    if (threadIdx.x < E_NUM) g_cnt[threadIdx.x] = 0;
}
__global__ void count_kernel(const int* __restrict__ ei) {
    int i = blockIdx.x * blockDim.x + threadIdx.x;
    if (i < S_SLOTS) atomicAdd(&g_cnt[ei[i]], 1);
}
__global__ void scan_kernel() {
    if (threadIdx.x == 0) {
        int acc = 0, nt = 0;
        for (int e = 0; e < E_NUM; e++) {
            g_off[e] = acc;
            int c = g_cnt[e];
            for (int mt = 0; mt * BM < c; mt++) {
                g_tile_e[nt] = e; g_tile_mt[nt] = mt; nt++;
            }
            acc += c;
        }
        g_ntiles = nt;
    }
}
__global__ void scatter_kernel(const int* __restrict__ ei,
                               const float* __restrict__ ew) {
    int e = blockIdx.x;
    __shared__ int warp_cnt[32];
    int t = threadIdx.x, lane = t & 31, w = t >> 5;
    int running = 0, off = g_off[e];
    for (int c0 = 0; c0 < S_SLOTS; c0 += 1024) {
        int i = c0 + t;
        int match = (ei[i] == e);
        unsigned mask = __ballot_sync(0xffffffffu, match);
        if (lane == 0) warp_cnt[w] = __popc(mask);
        __syncthreads();
        int wbase = 0, total = 0;
#pragma unroll
        for (int j = 0; j < 32; j++) {
            int c = warp_cnt[j];
            if (j < w) wbase += c;
            total += c;
        }
        if (match) {
            int rank = running + wbase + __popc(mask & ((1u << lane) - 1u));
            int slot = off + rank;
            g_tok[slot] = i >> 1;
            g_wt[slot]  = ew[i];
            g_slot[i]   = slot;
        }
        running += total;
        __syncthreads();
    }
}
// x f32 -> fp16 (vector of 8)
__global__ void xcast_kernel(const float* __restrict__ x) {
    int i = blockIdx.x * blockDim.x + threadIdx.x;
    if (i >= T_TOK * HS / 8) return;
    const float4 a = *(const float4*)(x + i * 8);
    const float4 b = *(const float4*)(x + i * 8 + 4);
    __half2 h0 = __floats2half2_rn(a.x, a.y);
    __half2 h1 = __floats2half2_rn(a.z, a.w);
    __half2 h2 = __floats2half2_rn(b.x, b.y);
    __half2 h3 = __floats2half2_rn(b.z, b.w);
    uint4 o;
    o.x = *reinterpret_cast<uint32_t*>(&h0);
    o.y = *reinterpret_cast<uint32_t*>(&h1);
    o.z = *reinterpret_cast<uint32_t*>(&h2);
    o.w = *reinterpret_cast<uint32_t*>(&h3);
    *(uint4*)(g_xh + (size_t)i * 8) = o;
}

// =====================================================================
// GEMM1: H = f16(gelu(gather(x) @ w1[e]))   block 256x128, warp 64x64
// grid (FFN/BN, MAX_TILES), 256 threads, dyn smem 58.4 KB
// =====================================================================
__global__ __launch_bounds__(256, 1)
void gemm1_f16(const float* __restrict__ w1) {
    const int ty = blockIdx.y;
    if (ty >= g_ntiles) return;
    const int e  = g_tile_e[ty];
    const int mt = g_tile_mt[ty];
    const int nt = blockIdx.x;
    const int cnt  = g_cnt[e];
    const int base = g_off[e] + mt * BM;

    extern __shared__ char smraw[];
    uint32_t* Bs = (uint32_t*)smraw;                    // [2][16][BROW]
    __half*   As = (__half*)(smraw + BS_BYTES);         // [2][BM][KST]
    __shared__ int rows[BM];

    const int t = threadIdx.x;
    rows[t] = (mt * BM + t < cnt) ? g_tok[base + t] : -1;
    __syncthreads();

    // A staging: 1 thread per row, 32 k-halves (4 x uint4)
    const int arow = rows[t];
    const __half* aptr = g_xh + (size_t)(arow < 0 ? 0 : arow) * HS;
    // B staging: thread -> half2-row bkk (k rows 2bkk,2bkk+1), 8 n values
    const int bkk = t >> 4, bn = (t & 15) * 8;
    const float* bptr = w1 + (size_t)e * HS * FFN
                           + (size_t)(2 * bkk) * FFN + nt * BN + bn;

    const int lane = t & 31, g = lane >> 2, tig = lane & 3;
    const int wm = (t >> 5 & 3) * 64;   // 4 warps along m
    const int wn = (t >> 7) * 64;       // 2 warps along n

    float acc[4][8][4];
#pragma unroll
    for (int mi = 0; mi < 4; mi++)
#pragma unroll
        for (int ni = 0; ni < 8; ni++)
#pragma unroll
            for (int j = 0; j < 4; j++) acc[mi][ni][j] = 0.f;

    uint4 ua[4];
    float4 rb00, rb01, rb10, rb11;
    {
        const uint4 uz = make_uint4(0, 0, 0, 0);
#pragma unroll
        for (int q = 0; q < 4; q++)
            ua[q] = (arow >= 0) ? *(const uint4*)(aptr + q * 8) : uz;
        rb00 = *(const float4*)(bptr);
        rb01 = *(const float4*)(bptr + 4);
        rb10 = *(const float4*)(bptr + FFN);
        rb11 = *(const float4*)(bptr + FFN + 4);
    }
#pragma unroll
    for (int q = 0; q < 4; q++)
        *(uint4*)&As[t * KST + q * 8] = ua[q];
    *(uint4*)&Bs[bkk * BROW + bn]     = packB(rb00, rb10);
    *(uint4*)&Bs[bkk * BROW + bn + 4] = packB(rb01, rb11);
    __syncthreads();

    const int S = HS / BK;   // 32 stages
    for (int s = 0; s < S; s++) {
        const int buf = s & 1;
        const bool more = (s + 1 < S);
        if (more) {
            const int k0 = (s + 1) * BK;
            const uint4 uz = make_uint4(0, 0, 0, 0);
#pragma unroll
            for (int q = 0; q < 4; q++)
                ua[q] = (arow >= 0) ? *(const uint4*)(aptr + k0 + q * 8) : uz;
            const float* bp = bptr + (size_t)k0 * FFN;
            rb00 = *(const float4*)(bp);
            rb01 = *(const float4*)(bp + 4);
            rb10 = *(const float4*)(bp + FFN);
            rb11 = *(const float4*)(bp + FFN + 4);
        }
        const __half*   Ab = As + buf * AS_HALF_PER_BUF;
        const uint32_t* Bb = Bs + buf * BS_WORDS_PER_BUF;
#pragma unroll
        for (int ks = 0; ks < 2; ks++) {
            const int kb = ks * 16;   // k offset in halves
            const int kk = ks * 8;    // B half2-row offset
            uint32_t a[4][4];
#pragma unroll
            for (int mi = 0; mi < 4; mi++) {
                const int m = wm + mi * 16 + g;
                a[mi][0] = *(const uint32_t*)&Ab[m * KST + kb + 2 * tig];
                a[mi][1] = *(const uint32_t*)&Ab[(m + 8) * KST + kb + 2 * tig];
                a[mi][2] = *(const uint32_t*)&Ab[m * KST + kb + 2 * tig + 8];
                a[mi][3] = *(const uint32_t*)&Ab[(m + 8) * KST + kb + 2 * tig + 8];
            }
#pragma unroll
            for (int ni = 0; ni < 8; ni++) {
                const int n = wn + ni * 8 + g;
                uint32_t b0 = Bb[(kk + tig) * BROW + n];
                uint32_t b1 = Bb[(kk + tig + 4) * BROW + n];
#pragma unroll
                for (int mi = 0; mi < 4; mi++)
                    mma_f16(acc[mi][ni], a[mi][0], a[mi][1], a[mi][2], a[mi][3],
                            b0, b1);
            }
        }
        if (more) {
            const int nb = buf ^ 1;
            __half*   An = As + nb * AS_HALF_PER_BUF;
            uint32_t* Bn = Bs + nb * BS_WORDS_PER_BUF;
#pragma unroll
            for (int q = 0; q < 4; q++)
                *(uint4*)&An[t * KST + q * 8] = ua[q];
            *(uint4*)&Bn[bkk * BROW + bn]     = packB(rb00, rb10);
            *(uint4*)&Bn[bkk * BROW + bn + 4] = packB(rb01, rb11);
            __syncthreads();
        }
    }

    // epilogue: gelu -> fp16 into H
    const int ncol0 = nt * BN + wn + 2 * tig;
#pragma unroll
    for (int mi = 0; mi < 4; mi++) {
        const int r0 = wm + mi * 16 + g;
        const int r1 = r0 + 8;
#pragma unroll
        for (int ni = 0; ni < 8; ni++) {
            const int nc = ncol0 + ni * 8;
            if (mt * BM + r0 < cnt) {
                __half2 o = __floats2half2_rn(gelu_tanh(acc[mi][ni][0]),
                                              gelu_tanh(acc[mi][ni][1]));
                *(__half2*)&g_H[(size_t)(base + r0) * FFN + nc] = o;
            }
            if (mt * BM + r1 < cnt) {
                __half2 o = __floats2half2_rn(gelu_tanh(acc[mi][ni][2]),
                                              gelu_tanh(acc[mi][ni][3]));
                *(__half2*)&g_H[(size_t)(base + r1) * FFN + nc] = o;
            }
        }
    }
}

// =====================================================================
// GEMM2: Y = wt * (H @ w2[e])   block 256x128, warp 64x64
// grid (HS/BN, MAX_TILES), 256 threads, dyn smem 58.4 KB
// =====================================================================
__global__ __launch_bounds__(256, 1)
void gemm2_f16(const float* __restrict__ w2) {
    const int ty = blockIdx.y;
    if (ty >= g_ntiles) return;
    const int e  = g_tile_e[ty];
    const int mt = g_tile_mt[ty];
    const int nt = blockIdx.x;
    const int cnt  = g_cnt[e];
    const int base = g_off[e] + mt * BM;

    extern __shared__ char smraw[];
    uint32_t* Bs = (uint32_t*)smraw;
    __half*   As = (__half*)(smraw + BS_BYTES);

    const int t = threadIdx.x;
    const bool avalid = (mt * BM + t) < cnt;
    const __half* aptr = g_H + (size_t)(base + (avalid ? t : 0)) * FFN;
    const int bkk = t >> 4, bn = (t & 15) * 8;
    const float* bptr = w2 + (size_t)e * FFN * HS
                           + (size_t)(2 * bkk) * HS + nt * BN + bn;

    const int lane = t & 31, g = lane >> 2, tig = lane & 3;
    const int wm = (t >> 5 & 3) * 64;
    const int wn = (t >> 7) * 64;

    float acc[4][8][4];
#pragma unroll
    for (int mi = 0; mi < 4; mi++)
#pragma unroll
        for (int ni = 0; ni < 8; ni++)
#pragma unroll
            for (int j = 0; j < 4; j++) acc[mi][ni][j] = 0.f;

    uint4 ua[4];
    float4 rb00, rb01, rb10, rb11;
    {
        const uint4 uz = make_uint4(0, 0, 0, 0);
#pragma unroll
        for (int q = 0; q < 4; q++)
            ua[q] = avalid ? *(const uint4*)(aptr + q * 8) : uz;
        rb00 = *(const float4*)(bptr);
        rb01 = *(const float4*)(bptr + 4);
        rb10 = *(const float4*)(bptr + HS);
        rb11 = *(const float4*)(bptr + HS + 4);
    }
#pragma unroll
    for (int q = 0; q < 4; q++)
        *(uint4*)&As[t * KST + q * 8] = ua[q];
    *(uint4*)&Bs[bkk * BROW + bn]     = packB(rb00, rb10);
    *(uint4*)&Bs[bkk * BROW + bn + 4] = packB(rb01, rb11);
    __syncthreads();

    const int S = FFN / BK;   // 128 stages
    for (int s = 0; s < S; s++) {
        const int buf = s & 1;
        const bool more = (s + 1 < S);
        if (more) {
            const int k0 = (s + 1) * BK;
            const uint4 uz = make_uint4(0, 0, 0, 0);
#pragma unroll
            for (int q = 0; q < 4; q++)
                ua[q] = avalid ? *(const uint4*)(aptr + k0 + q * 8) : uz;
            const float* bp = bptr + (size_t)k0 * HS;
            rb00 = *(const float4*)(bp);
            rb01 = *(const float4*)(bp + 4);
            rb10 = *(const float4*)(bp + HS);
            rb11 = *(const float4*)(bp + HS + 4);
        }
        const __half*   Ab = As + buf * AS_HALF_PER_BUF;
        const uint32_t* Bb = Bs + buf * BS_WORDS_PER_BUF;
#pragma unroll
        for (int ks = 0; ks < 2; ks++) {
            const int kb = ks * 16;
            const int kk = ks * 8;
            uint32_t a[4][4];
#pragma unroll
            for (int mi = 0; mi < 4; mi++) {
                const int m = wm + mi * 16 + g;
                a[mi][0] = *(const uint32_t*)&Ab[m * KST + kb + 2 * tig];
                a[mi][1] = *(const uint32_t*)&Ab[(m + 8) * KST + kb + 2 * tig];
                a[mi][2] = *(const uint32_t*)&Ab[m * KST + kb + 2 * tig + 8];
                a[mi][3] = *(const uint32_t*)&Ab[(m + 8) * KST + kb + 2 * tig + 8];
            }
#pragma unroll
            for (int ni = 0; ni < 8; ni++) {
                const int n = wn + ni * 8 + g;
                uint32_t b0 = Bb[(kk + tig) * BROW + n];
                uint32_t b1 = Bb[(kk + tig + 4) * BROW + n];
#pragma unroll
                for (int mi = 0; mi < 4; mi++)
                    mma_f16(acc[mi][ni], a[mi][0], a[mi][1], a[mi][2], a[mi][3],
                            b0, b1);
            }
        }
        if (more) {
            const int nb = buf ^ 1;
            __half*   An = As + nb * AS_HALF_PER_BUF;
            uint32_t* Bn = Bs + nb * BS_WORDS_PER_BUF;
#pragma unroll
            for (int q = 0; q < 4; q++)
                *(uint4*)&An[t * KST + q * 8] = ua[q];
            *(uint4*)&Bn[bkk * BROW + bn]     = packB(rb00, rb10);
            *(uint4*)&Bn[bkk * BROW + bn + 4] = packB(rb01, rb11);
            __syncthreads();
        }
    }

    // epilogue: gate-weight scale -> f32 Y
    const int ncol0 = nt * BN + wn + 2 * tig;
#pragma unroll
    for (int mi = 0; mi < 4; mi++) {
        const int r0 = wm + mi * 16 + g;
        const int r1 = r0 + 8;
#pragma unroll
        for (int ni = 0; ni < 8; ni++) {
            const int nc = ncol0 + ni * 8;
            if (mt * BM + r0 < cnt) {
                float w = g_wt[base + r0];
                float2 o = make_float2(w * acc[mi][ni][0], w * acc[mi][ni][1]);
                *(float2*)&g_Y[(size_t)(base + r0) * HS + nc] = o;
            }
            if (mt * BM + r1 < cnt) {
                float w = g_wt[base + r1];
                float2 o = make_float2(w * acc[mi][ni][2], w * acc[mi][ni][3]);
                *(float2*)&g_Y[(size_t)(base + r1) * HS + nc] = o;
            }
        }
    }
}

// ---------------- combine: out[t] = Y[slot(t,0)] + Y[slot(t,1)] ----------------
__global__ void combine_kernel(float* __restrict__ out) {
    int i = blockIdx.x * blockDim.x + threadIdx.x;
    if (i >= T_TOK * HS / 4) return;
    int tok = i / (HS / 4);
    int h4  = i - tok * (HS / 4);
    int s0 = g_slot[2 * tok];
    int s1 = g_slot[2 * tok + 1];
    const float4 y0 = *(const float4*)(g_Y + (size_t)s0 * HS + h4 * 4);
    const float4 y1 = *(const float4*)(g_Y + (size_t)s1 * HS + h4 * 4);
    float4 o = make_float4(y0.x + y1.x, y0.y + y1.y, y0.z + y1.z, y0.w + y1.w);
    reinterpret_cast<float4*>(out)[i] = o;
}

// ---------------- launch ----------------
extern "C" void kernel_launch(void* const* d_in, const int* in_sizes, int n_in,
                              void* d_out, int out_size) {
    const float* x  = (const float*)d_in[0];   // [4096, 1024]
    const float* ew = (const float*)d_in[1];   // [4096, 2]
    const int*   ei = (const int*)  d_in[2];   // [4096, 2]
    const float* w1 = (const float*)d_in[3];   // [8, 1024, 4096]
    const float* w2 = (const float*)d_in[4];   // [8, 4096, 1024]
    float* out = (float*)d_out;
    (void)in_sizes; (void)n_in; (void)out_size;

    static bool attr_done = false;
    if (!attr_done) {
        cudaFuncSetAttribute(gemm1_f16,
                             cudaFuncAttributeMaxDynamicSharedMemorySize, SMEM_BYTES);
        cudaFuncSetAttribute(gemm2_f16,
                             cudaFuncAttributeMaxDynamicSharedMemorySize, SMEM_BYTES);
        attr_done = true;
    }

    zero_cnt_kernel<<<1, 32>>>();
    count_kernel<<<(S_SLOTS + 255) / 256, 256>>>(ei);
    scan_kernel<<<1, 32>>>();
    scatter_kernel<<<E_NUM, 1024>>>(ei, ew);
    xcast_kernel<<<(T_TOK * HS / 8 + 255) / 256, 256>>>(x);
    gemm1_f16<<<dim3(FFN / BN, MAX_TILES), 256, SMEM_BYTES>>>(w1);
    gemm2_f16<<<dim3(HS / BN, MAX_TILES), 256, SMEM_BYTES>>>(w2);
    combine_kernel<<<(T_TOK * HS / 4 + 255) / 256, 256>>>(out);
}